// round 5
// baseline (speedup 1.0000x reference)
#include <cuda_runtime.h>
#include <cstdint>
#include <cstddef>

#define HCN 4
#define CN  2048
#define TOK 4096
#define KDIM 8192
#define NLOG 24

__device__ float g_xin [TOK * CN];
__device__ float g_fout[TOK * CN];
__device__ float g_wt  [CN * CN];   // tf32-rounded W, same [k][n] layout
__device__ float g_coef[TOK * NLOG];

__device__ __forceinline__ uint32_t smem_u32(const void* p) {
    uint32_t a;
    asm("{ .reg .u64 t; cvta.to.shared.u64 t, %1; cvt.u32.u64 %0, t; }" : "=r"(a) : "l"(p));
    return a;
}
__device__ __forceinline__ float to_tf32(float v) {
    uint32_t r; asm("cvt.rna.tf32.f32 %0, %1;" : "=r"(r) : "f"(v));
    return __uint_as_float(r);
}
__device__ __forceinline__ void cp16(uint32_t s, const float* g) {
    asm volatile("cp.async.cg.shared.global [%0], [%1], 16;" :: "r"(s), "l"(g));
}
__device__ __forceinline__ void mma_tf32(float* c, const uint32_t* a, const uint32_t* b) {
    asm volatile(
        "mma.sync.aligned.m16n8k8.row.col.f32.tf32.tf32.f32 "
        "{%0,%1,%2,%3}, {%4,%5,%6,%7}, {%8,%9}, {%0,%1,%2,%3};"
        : "+f"(c[0]), "+f"(c[1]), "+f"(c[2]), "+f"(c[3])
        : "r"(a[0]), "r"(a[1]), "r"(a[2]), "r"(a[3]), "r"(b[0]), "r"(b[1]));
}

// ---------------- K1: W -> tf32-rounded copy (same layout) ----------------
__global__ __launch_bounds__(256) void k_wprep(const float* __restrict__ W) {
    int i = (blockIdx.x * 256 + threadIdx.x) * 4;
    float4 v = *(const float4*)(W + i);
    v.x = to_tf32(v.x); v.y = to_tf32(v.y); v.z = to_tf32(v.z); v.w = to_tf32(v.w);
    *(float4*)(g_wt + i) = v;
}

// ---------------- K2: per-token logits ----------------
__global__ __launch_bounds__(128) void k_coeffs(const float* __restrict__ x,
                                                const float* __restrict__ phi,
                                                const float* __restrict__ bias) {
    __shared__ float phi_s[256 * 25];
    const int tid = threadIdx.x, lane = tid & 31, w = tid >> 5;
    const int t0 = blockIdx.x * 16 + w * 4;
    float a0[NLOG], a1[NLOG], a2[NLOG], a3[NLOG];
#pragma unroll
    for (int j = 0; j < NLOG; j++) { a0[j] = a1[j] = a2[j] = a3[j] = 0.f; }
    float s0 = 0.f, s1 = 0.f, s2 = 0.f, s3 = 0.f;
    const float* xr0 = x + (size_t)t0 * KDIM;
    const float* xr1 = xr0 + KDIM;
    const float* xr2 = xr1 + KDIM;
    const float* xr3 = xr2 + KDIM;
    for (int kc = 0; kc < KDIM; kc += 256) {
        for (int i = tid; i < 256 * NLOG; i += 128) {
            int k = i / NLOG, j = i - k * NLOG;
            phi_s[k * 25 + j] = phi[(size_t)(kc + k) * NLOG + j];
        }
        __syncthreads();
#pragma unroll 4
        for (int i = 0; i < 8; i++) {
            int kk = i * 32 + lane;
            int k = kc + kk;
            float x0 = xr0[k], x1 = xr1[k], x2 = xr2[k], x3 = xr3[k];
            s0 += x0 * x0; s1 += x1 * x1; s2 += x2 * x2; s3 += x3 * x3;
            const float* pr = &phi_s[kk * 25];
#pragma unroll
            for (int j = 0; j < NLOG; j++) {
                float p = pr[j];
                a0[j] += x0 * p; a1[j] += x1 * p; a2[j] += x2 * p; a3[j] += x3 * p;
            }
        }
        __syncthreads();
    }
#pragma unroll
    for (int off = 16; off > 0; off >>= 1) {
        s0 += __shfl_down_sync(~0u, s0, off); s1 += __shfl_down_sync(~0u, s1, off);
        s2 += __shfl_down_sync(~0u, s2, off); s3 += __shfl_down_sync(~0u, s3, off);
#pragma unroll
        for (int j = 0; j < NLOG; j++) {
            a0[j] += __shfl_down_sync(~0u, a0[j], off);
            a1[j] += __shfl_down_sync(~0u, a1[j], off);
            a2[j] += __shfl_down_sync(~0u, a2[j], off);
            a3[j] += __shfl_down_sync(~0u, a3[j], off);
        }
    }
    if (lane == 0) {
        const float inv = 1.0f / (float)KDIM;
        float r0 = rsqrtf(s0 * inv + 1e-6f), r1 = rsqrtf(s1 * inv + 1e-6f);
        float r2 = rsqrtf(s2 * inv + 1e-6f), r3 = rsqrtf(s3 * inv + 1e-6f);
#pragma unroll
        for (int j = 0; j < NLOG; j++) {
            float bj = bias[j];
            g_coef[(size_t)t0 * NLOG + j]           = a0[j] * r0 + bj;
            g_coef[(size_t)(t0 + 1) * NLOG + j]     = a1[j] * r1 + bj;
            g_coef[(size_t)(t0 + 2) * NLOG + j]     = a2[j] * r2 + bj;
            g_coef[(size_t)(t0 + 3) * NLOG + j]     = a3[j] * r3 + bj;
        }
    }
}

// ---------------- K3: gates + Sinkhorn ----------------
__global__ void k_sink(const float* __restrict__ a_pre, const float* __restrict__ a_post,
                       const float* __restrict__ a_res) {
    int t = blockIdx.x * blockDim.x + threadIdx.x;
    if (t >= TOK) return;
    float L[NLOG];
#pragma unroll
    for (int j = 0; j < NLOG; j++) L[j] = g_coef[(size_t)t * NLOG + j];
    float ap = a_pre[0], aq = a_post[0], ar = a_res[0];
    float m[16];
#pragma unroll
    for (int h = 0; h < 4; h++) {
        L[h]     = 1.0f / (1.0f + expf(-ap * L[h])) + 1e-4f;
        L[4 + h] = 2.0f / (1.0f + expf(-aq * L[4 + h]));
    }
#pragma unroll
    for (int i = 0; i < 16; i++) m[i] = expf(ar * L[8 + i]);
#pragma unroll
    for (int it = 0; it < 8; it++) {
#pragma unroll
        for (int o = 0; o < 4; o++) {
            float inv = 1.0f / (m[o*4] + m[o*4+1] + m[o*4+2] + m[o*4+3] + 1e-6f);
            m[o*4] *= inv; m[o*4+1] *= inv; m[o*4+2] *= inv; m[o*4+3] *= inv;
        }
#pragma unroll
        for (int i = 0; i < 4; i++) {
            float inv = 1.0f / (m[i] + m[4+i] + m[8+i] + m[12+i] + 1e-6f);
            m[i] *= inv; m[4+i] *= inv; m[8+i] *= inv; m[12+i] *= inv;
        }
    }
#pragma unroll
    for (int j = 0; j < 8; j++) g_coef[(size_t)t * NLOG + j] = L[j];
#pragma unroll
    for (int i = 0; i < 16; i++) g_coef[(size_t)t * NLOG + 8 + i] = m[i];
}

// ---------------- K4: x_in (tf32-rounded) ----------------
__global__ __launch_bounds__(256) void k_xin(const float* __restrict__ x) {
    const int t = blockIdx.x >> 1;
    const int c = ((blockIdx.x & 1) * 256 + threadIdx.x) * 4;
    __shared__ float hp[4];
    if (threadIdx.x < 4) hp[threadIdx.x] = g_coef[(size_t)t * NLOG + threadIdx.x];
    __syncthreads();
    const float* xb = x + (size_t)t * KDIM + c;
    float4 v0 = *(const float4*)xb;
    float4 v1 = *(const float4*)(xb + CN);
    float4 v2 = *(const float4*)(xb + 2 * CN);
    float4 v3 = *(const float4*)(xb + 3 * CN);
    float h0 = hp[0], h1 = hp[1], h2 = hp[2], h3 = hp[3];
    float4 s;
    s.x = to_tf32(h0 * v0.x + h1 * v1.x + h2 * v2.x + h3 * v3.x);
    s.y = to_tf32(h0 * v0.y + h1 * v1.y + h2 * v2.y + h3 * v3.y);
    s.z = to_tf32(h0 * v0.z + h1 * v1.z + h2 * v2.z + h3 * v3.z);
    s.w = to_tf32(h0 * v0.w + h1 * v1.w + h2 * v2.w + h3 * v3.w);
    *(float4*)(g_xin + (size_t)t * CN + c) = s;
}

// ---------------- K5: tf32 mma.sync GEMM  g_fout = g_xin @ W + Wb ----------
// CTA tile 128x128, K chunk 32, 4-stage cp.async pipeline.
// smem per stage: A [128][36] floats (4608) + B [32][136] floats (4352) = 8960 fl
static constexpr int ST_FLOATS = 8960;
static constexpr int B_OFF     = 4608;
static constexpr int NSTAGE    = 4;
static constexpr uint32_t GEMM_SMEM = NSTAGE * ST_FLOATS * 4;   // 143360 B
static constexpr int NKCH = CN / 32;                            // 64

__global__ __launch_bounds__(256, 1) void k_gemm(const float* __restrict__ Wb) {
    extern __shared__ __align__(16) float smf[];
    const uint32_t sbase = smem_u32(smf);
    const int tid = threadIdx.x, lane = tid & 31, wid = tid >> 5;
    const int wm = wid >> 2, wn = wid & 3;        // warp grid 2(m) x 4(n)
    const int m0 = blockIdx.y * 128, n0 = blockIdx.x * 128;
    const int lr = lane >> 2, lc = lane & 3;

    auto load_stage = [&](int kc, int st) {
        const int k0 = kc * 32;
        const uint32_t sa = sbase + (uint32_t)(st * ST_FLOATS) * 4u;
#pragma unroll
        for (int i = 0; i < 4; i++) {             // A: 128 rows x 32 fl
            int seg = tid + 256 * i, r = seg >> 3, cs = seg & 7;
            cp16(sa + (uint32_t)(r * 36 + cs * 4) * 4u,
                 g_xin + (size_t)(m0 + r) * CN + k0 + cs * 4);
        }
        const uint32_t sb = sa + B_OFF * 4u;
#pragma unroll
        for (int i = 0; i < 4; i++) {             // B: 32 rows x 128 fl
            int seg = tid + 256 * i, r = seg >> 5, cs = seg & 31;
            cp16(sb + (uint32_t)(r * 136 + cs * 4) * 4u,
                 g_wt + (size_t)(k0 + r) * CN + n0 + cs * 4);
        }
        asm volatile("cp.async.commit_group;" ::: "memory");
    };

    load_stage(0, 0);
    load_stage(1, 1);
    load_stage(2, 2);

    float c[4][4][4];
#pragma unroll
    for (int i = 0; i < 4; i++)
#pragma unroll
        for (int j = 0; j < 4; j++)
#pragma unroll
            for (int k = 0; k < 4; k++) c[i][j][k] = 0.f;

    for (int kt = 0; kt < NKCH; kt++) {
        asm volatile("cp.async.wait_group 2;" ::: "memory");
        __syncthreads();
        if (kt + 3 < NKCH) load_stage(kt + 3, (kt + 3) & 3);

        const uint32_t* sA = (const uint32_t*)smf + (kt & 3) * ST_FLOATS;
        const uint32_t* sB = sA + B_OFF;
#pragma unroll
        for (int s = 0; s < 4; s++) {
            const int ak = s * 8 + lc;
            uint32_t a[4][4];
#pragma unroll
            for (int mt = 0; mt < 4; mt++) {
                const uint32_t* p = sA + (wm * 64 + mt * 16 + lr) * 36 + ak;
                a[mt][0] = p[0];
                a[mt][1] = p[8 * 36];
                a[mt][2] = p[4];
                a[mt][3] = p[8 * 36 + 4];
            }
            uint32_t b[4][2];
#pragma unroll
            for (int nt = 0; nt < 4; nt++) {
                const uint32_t* q = sB + ak * 136 + wn * 32 + nt * 8 + lr;
                b[nt][0] = q[0];
                b[nt][1] = q[4 * 136];
            }
#pragma unroll
            for (int mt = 0; mt < 4; mt++)
#pragma unroll
                for (int nt = 0; nt < 4; nt++)
                    mma_tf32(c[mt][nt], a[mt], b[nt]);
        }
    }

    // epilogue: c regs -> g_fout (+Wb). c0,c1 at (row, 2lc), c2,c3 at (row+8, 2lc)
#pragma unroll
    for (int nt = 0; nt < 4; nt++) {
        const int col = n0 + wn * 32 + nt * 8 + lc * 2;
        const float wb0 = Wb[col], wb1 = Wb[col + 1];
#pragma unroll
        for (int mt = 0; mt < 4; mt++) {
            const int row = m0 + wm * 64 + mt * 16 + lr;
            float2 v0 = make_float2(c[mt][nt][0] + wb0, c[mt][nt][1] + wb1);
            float2 v1 = make_float2(c[mt][nt][2] + wb0, c[mt][nt][3] + wb1);
            *(float2*)(g_fout + (size_t)row * CN + col) = v0;
            *(float2*)(g_fout + (size_t)(row + 8) * CN + col) = v1;
        }
    }
}

// ---------------- K6: output ----------------
__global__ __launch_bounds__(256) void k_out(const float* __restrict__ x, float* __restrict__ out) {
    const int t = blockIdx.x >> 1;
    const int c = ((blockIdx.x & 1) * 256 + threadIdx.x) * 4;
    __shared__ float cf[NLOG];
    if (threadIdx.x < NLOG) cf[threadIdx.x] = g_coef[(size_t)t * NLOG + threadIdx.x];
    __syncthreads();
    const float* xb = x + (size_t)t * KDIM + c;
    float4 v0 = *(const float4*)xb;
    float4 v1 = *(const float4*)(xb + CN);
    float4 v2 = *(const float4*)(xb + 2 * CN);
    float4 v3 = *(const float4*)(xb + 3 * CN);
    float4 f  = *(const float4*)(g_fout + (size_t)t * CN + c);
#pragma unroll
    for (int o = 0; o < 4; o++) {
        float r0 = cf[8 + o * 4], r1 = cf[9 + o * 4], r2 = cf[10 + o * 4], r3 = cf[11 + o * 4];
        float hp = cf[4 + o];
        float4 rr;
        rr.x = r0 * v0.x + r1 * v1.x + r2 * v2.x + r3 * v3.x + hp * f.x;
        rr.y = r0 * v0.y + r1 * v1.y + r2 * v2.y + r3 * v3.y + hp * f.y;
        rr.z = r0 * v0.z + r1 * v1.z + r2 * v2.z + r3 * v3.z + hp * f.z;
        rr.w = r0 * v0.w + r1 * v1.w + r2 * v2.w + r3 * v3.w + hp * f.w;
        *(float4*)(out + (size_t)t * KDIM + o * CN + c) = rr;
    }
}

extern "C" void kernel_launch(void* const* d_in, const int* in_sizes, int n_in,
                              void* d_out, int out_size) {
    const float* x      = (const float*)d_in[0];
    const float* phi    = (const float*)d_in[1];
    const float* b      = (const float*)d_in[2];
    const float* a_pre  = (const float*)d_in[3];
    const float* a_post = (const float*)d_in[4];
    const float* a_res  = (const float*)d_in[5];
    const float* W      = (const float*)d_in[6];
    const float* Wb     = (const float*)d_in[7];
    float* out = (float*)d_out;

    cudaFuncSetAttribute(k_gemm, cudaFuncAttributeMaxDynamicSharedMemorySize, GEMM_SMEM);

    k_wprep<<<CN * CN / 1024, 256>>>(W);
    k_coeffs<<<TOK / 16, 128>>>(x, phi, b);
    k_sink<<<TOK / 256, 256>>>(a_pre, a_post, a_res);
    k_xin<<<TOK * 2, 256>>>(x);
    k_gemm<<<dim3(CN / 128, TOK / 128), 256, GEMM_SMEM>>>(Wb);
    k_out<<<TOK * 2, 256>>>(x, out);
}

// round 6
// speedup vs baseline: 1.2541x; 1.2541x over previous
#include <cuda_runtime.h>
#include <cstdint>
#include <cstddef>

#define CN  2048
#define TOK 4096
#define KDIM 8192
#define NLOG 24

__device__ float g_xin [TOK * CN];
__device__ float g_wt  [CN * CN];    // W^T, tf32-rounded, [n][k]
__device__ float g_coef[TOK * NLOG];

__device__ __forceinline__ uint32_t smem_u32(const void* p) {
    uint32_t a;
    asm("{ .reg .u64 t; cvta.to.shared.u64 t, %1; cvt.u32.u64 %0, t; }" : "=r"(a) : "l"(p));
    return a;
}
__device__ __forceinline__ float to_tf32(float v) {
    uint32_t r; asm("cvt.rna.tf32.f32 %0, %1;" : "=r"(r) : "f"(v));
    return __uint_as_float(r);
}
__device__ __forceinline__ void cp16(uint32_t s, const float* g) {
    asm volatile("cp.async.cg.shared.global [%0], [%1], 16;" :: "r"(s), "l"(g));
}
__device__ __forceinline__ void ldsm_x4(uint32_t addr, uint32_t& r0, uint32_t& r1,
                                        uint32_t& r2, uint32_t& r3) {
    asm volatile("ldmatrix.sync.aligned.m8n8.x4.shared.b16 {%0,%1,%2,%3}, [%4];"
        : "=r"(r0), "=r"(r1), "=r"(r2), "=r"(r3) : "r"(addr));
}
__device__ __forceinline__ void ldsm_x2(uint32_t addr, uint32_t& r0, uint32_t& r1) {
    asm volatile("ldmatrix.sync.aligned.m8n8.x2.shared.b16 {%0,%1}, [%2];"
        : "=r"(r0), "=r"(r1) : "r"(addr));
}
__device__ __forceinline__ void mma_tf32(float* c, const uint32_t* a, const uint32_t* b) {
    asm volatile(
        "mma.sync.aligned.m16n8k8.row.col.f32.tf32.tf32.f32 "
        "{%0,%1,%2,%3}, {%4,%5,%6,%7}, {%8,%9}, {%0,%1,%2,%3};"
        : "+f"(c[0]), "+f"(c[1]), "+f"(c[2]), "+f"(c[3])
        : "r"(a[0]), "r"(a[1]), "r"(a[2]), "r"(a[3]), "r"(b[0]), "r"(b[1]));
}

// ---------------- K1: W^T (tf32-rounded) ----------------
__global__ void k_transpose(const float* __restrict__ W) {
    __shared__ float t[32][33];
    int bx = blockIdx.x, by = blockIdx.y, tx = threadIdx.x, ty = threadIdx.y;
#pragma unroll
    for (int i = 0; i < 32; i += 8)
        t[ty + i][tx] = W[(size_t)(by * 32 + ty + i) * CN + bx * 32 + tx];
    __syncthreads();
#pragma unroll
    for (int i = 0; i < 32; i += 8)
        g_wt[(size_t)(bx * 32 + ty + i) * CN + by * 32 + tx] = to_tf32(t[tx][ty + i]);
}

// ---------------- K2: logits + gates + sinkhorn (fused) ----------------
#define FINISH_TOKEN(dst, A, rr) do {                                         \
    float L[NLOG];                                                            \
    _Pragma("unroll") for (int j = 0; j < NLOG; j++) L[j] = A[j] * (rr) + bias[j]; \
    _Pragma("unroll") for (int h = 0; h < 4; h++) {                           \
        (dst)[h]     = 1.0f / (1.0f + expf(-ap * L[h])) + 1e-4f;              \
        (dst)[4 + h] = 2.0f / (1.0f + expf(-aq * L[4 + h]));                  \
    }                                                                         \
    float m[16];                                                              \
    _Pragma("unroll") for (int i = 0; i < 16; i++) m[i] = expf(ar * L[8 + i]);\
    _Pragma("unroll") for (int it = 0; it < 8; it++) {                        \
        _Pragma("unroll") for (int o = 0; o < 4; o++) {                       \
            float inv = 1.0f / (m[o*4] + m[o*4+1] + m[o*4+2] + m[o*4+3] + 1e-6f); \
            m[o*4] *= inv; m[o*4+1] *= inv; m[o*4+2] *= inv; m[o*4+3] *= inv; \
        }                                                                     \
        _Pragma("unroll") for (int i = 0; i < 4; i++) {                       \
            float inv = 1.0f / (m[i] + m[4+i] + m[8+i] + m[12+i] + 1e-6f);    \
            m[i] *= inv; m[4+i] *= inv; m[8+i] *= inv; m[12+i] *= inv;        \
        }                                                                     \
    }                                                                         \
    _Pragma("unroll") for (int i = 0; i < 16; i++) (dst)[8 + i] = m[i];       \
} while (0)

__global__ __launch_bounds__(128) void k_coeffs(const float* __restrict__ x,
                                                const float* __restrict__ phi,
                                                const float* __restrict__ bias,
                                                const float* __restrict__ a_pre,
                                                const float* __restrict__ a_post,
                                                const float* __restrict__ a_res) {
    __shared__ float phi_s[256 * 25];
    const int tid = threadIdx.x, lane = tid & 31, w = tid >> 5;
    const int t0 = blockIdx.x * 16 + w * 4;
    float a0[NLOG], a1[NLOG], a2[NLOG], a3[NLOG];
#pragma unroll
    for (int j = 0; j < NLOG; j++) { a0[j] = a1[j] = a2[j] = a3[j] = 0.f; }
    float s0 = 0.f, s1 = 0.f, s2 = 0.f, s3 = 0.f;
    const float* xr0 = x + (size_t)t0 * KDIM;
    const float* xr1 = xr0 + KDIM;
    const float* xr2 = xr1 + KDIM;
    const float* xr3 = xr2 + KDIM;
    for (int kc = 0; kc < KDIM; kc += 256) {
        for (int i = tid; i < 256 * NLOG; i += 128) {
            int k = i / NLOG, j = i - k * NLOG;
            phi_s[k * 25 + j] = phi[(size_t)(kc + k) * NLOG + j];
        }
        __syncthreads();
#pragma unroll 4
        for (int i = 0; i < 8; i++) {
            int kk = i * 32 + lane;
            int k = kc + kk;
            float x0 = xr0[k], x1 = xr1[k], x2 = xr2[k], x3 = xr3[k];
            s0 += x0 * x0; s1 += x1 * x1; s2 += x2 * x2; s3 += x3 * x3;
            const float* pr = &phi_s[kk * 25];
#pragma unroll
            for (int j = 0; j < NLOG; j++) {
                float p = pr[j];
                a0[j] += x0 * p; a1[j] += x1 * p; a2[j] += x2 * p; a3[j] += x3 * p;
            }
        }
        __syncthreads();
    }
#pragma unroll
    for (int off = 16; off > 0; off >>= 1) {
        s0 += __shfl_down_sync(~0u, s0, off); s1 += __shfl_down_sync(~0u, s1, off);
        s2 += __shfl_down_sync(~0u, s2, off); s3 += __shfl_down_sync(~0u, s3, off);
#pragma unroll
        for (int j = 0; j < NLOG; j++) {
            a0[j] += __shfl_down_sync(~0u, a0[j], off);
            a1[j] += __shfl_down_sync(~0u, a1[j], off);
            a2[j] += __shfl_down_sync(~0u, a2[j], off);
            a3[j] += __shfl_down_sync(~0u, a3[j], off);
        }
    }
    if (lane == 0) {
        const float inv = 1.0f / (float)KDIM;
        const float ap = a_pre[0], aq = a_post[0], ar = a_res[0];
        float r0 = rsqrtf(s0 * inv + 1e-6f), r1 = rsqrtf(s1 * inv + 1e-6f);
        float r2 = rsqrtf(s2 * inv + 1e-6f), r3 = rsqrtf(s3 * inv + 1e-6f);
        FINISH_TOKEN(g_coef + (size_t)t0 * NLOG,       a0, r0);
        FINISH_TOKEN(g_coef + (size_t)(t0 + 1) * NLOG, a1, r1);
        FINISH_TOKEN(g_coef + (size_t)(t0 + 2) * NLOG, a2, r2);
        FINISH_TOKEN(g_coef + (size_t)(t0 + 3) * NLOG, a3, r3);
    }
}

// ---------------- K3: x_in (tf32-rounded) ----------------
__global__ __launch_bounds__(256) void k_xin(const float* __restrict__ x) {
    const int t = blockIdx.x >> 1;
    const int c = ((blockIdx.x & 1) * 256 + threadIdx.x) * 4;
    __shared__ float hp[4];
    if (threadIdx.x < 4) hp[threadIdx.x] = g_coef[(size_t)t * NLOG + threadIdx.x];
    __syncthreads();
    const float* xb = x + (size_t)t * KDIM + c;
    float4 v0 = *(const float4*)xb;
    float4 v1 = *(const float4*)(xb + CN);
    float4 v2 = *(const float4*)(xb + 2 * CN);
    float4 v3 = *(const float4*)(xb + 3 * CN);
    float h0 = hp[0], h1 = hp[1], h2 = hp[2], h3 = hp[3];
    float4 s;
    s.x = to_tf32(h0 * v0.x + h1 * v1.x + h2 * v2.x + h3 * v3.x);
    s.y = to_tf32(h0 * v0.y + h1 * v1.y + h2 * v2.y + h3 * v3.y);
    s.z = to_tf32(h0 * v0.z + h1 * v1.z + h2 * v2.z + h3 * v3.z);
    s.w = to_tf32(h0 * v0.w + h1 * v1.w + h2 * v2.w + h3 * v3.w);
    *(float4*)(g_xin + (size_t)t * CN + c) = s;
}

// ---------------- K4: GEMM + fused output ----------------
// smem stage: A [128][36] fl + B [128][36] fl = 9216 floats (36864 B), 3 stages
static constexpr int ST_FLOATS = 9216;
static constexpr int B_OFF     = 4608;
static constexpr uint32_t GEMM_SMEM = 3u * ST_FLOATS * 4u;   // 110592 B
static constexpr int NKCH = CN / 32;                          // 64

__global__ __launch_bounds__(256, 2) void k_gemm(const float* __restrict__ x,
                                                 const float* __restrict__ Wb,
                                                 float* __restrict__ out) {
    extern __shared__ __align__(16) float smf[];
    const uint32_t sbase = smem_u32(smf);
    const int tid = threadIdx.x, lane = tid & 31, wid = tid >> 5;
    const int wm = wid >> 2, wn = wid & 3;          // 2(m) x 4(n) warp grid
    const int m0 = blockIdx.y * 128, n0 = blockIdx.x * 128;
    const int lr = lane >> 2, lc = lane & 3;

    auto load_stage = [&](int kc, int st) {
        const int k0 = kc * 32;
        const uint32_t sa = sbase + (uint32_t)(st * ST_FLOATS) * 4u;
#pragma unroll
        for (int i = 0; i < 4; i++) {
            int seg = tid + 256 * i, r = seg >> 3, cs = seg & 7;
            cp16(sa + (uint32_t)(r * 36 + cs * 4) * 4u,
                 g_xin + (size_t)(m0 + r) * CN + k0 + cs * 4);
        }
        const uint32_t sb = sa + B_OFF * 4u;
#pragma unroll
        for (int i = 0; i < 4; i++) {
            int seg = tid + 256 * i, r = seg >> 3, cs = seg & 7;
            cp16(sb + (uint32_t)(r * 36 + cs * 4) * 4u,
                 g_wt + (size_t)(n0 + r) * CN + k0 + cs * 4);
        }
        asm volatile("cp.async.commit_group;" ::: "memory");
    };

    load_stage(0, 0);
    load_stage(1, 1);

    // lane-dependent ldmatrix offsets (bytes)
    const uint32_t a_lane = (uint32_t)((((lane & 7) | ((lane >> 1) & 8)) * 36 +
                                        ((lane >> 3) & 1) * 4) * 4);
    const uint32_t b_lane = (uint32_t)(((lane & 7) * 36 + ((lane >> 3) & 1) * 4) * 4);

    float c[4][4][4];
#pragma unroll
    for (int i = 0; i < 4; i++)
#pragma unroll
        for (int j = 0; j < 4; j++)
#pragma unroll
            for (int k = 0; k < 4; k++) c[i][j][k] = 0.f;

    for (int kt = 0; kt < NKCH; kt++) {
        asm volatile("cp.async.wait_group 1;" ::: "memory");
        __syncthreads();
        if (kt + 2 < NKCH) load_stage(kt + 2, (kt + 2) % 3);
        else asm volatile("cp.async.commit_group;" ::: "memory");

        const uint32_t sa = sbase + (uint32_t)((kt % 3) * ST_FLOATS) * 4u;
        const uint32_t abase = sa + (uint32_t)(wm * 64 * 36) * 4u + a_lane;
        const uint32_t bbase = sa + (uint32_t)(B_OFF + wn * 32 * 36) * 4u + b_lane;
#pragma unroll
        for (int s = 0; s < 4; s++) {
            uint32_t a4[4][4], b2[4][2];
#pragma unroll
            for (int mt = 0; mt < 4; mt++) {
                uint32_t r0, r1, r2, r3;
                ldsm_x4(abase + (uint32_t)(mt * 16 * 36 * 4 + s * 32), r0, r1, r2, r3);
                a4[mt][0] = r0; a4[mt][1] = r2; a4[mt][2] = r1; a4[mt][3] = r3;
            }
#pragma unroll
            for (int nt = 0; nt < 4; nt++)
                ldsm_x2(bbase + (uint32_t)(nt * 8 * 36 * 4 + s * 32), b2[nt][0], b2[nt][1]);
#pragma unroll
            for (int mt = 0; mt < 4; mt++)
#pragma unroll
                for (int nt = 0; nt < 4; nt++)
                    mma_tf32(c[mt][nt], a4[mt], b2[nt]);
        }
    }

    // stage this CTA's coefs (128 tokens x 24 fl) into smem
    __syncthreads();
    {
        float4* cs4 = (float4*)smf;
        const float4* gc4 = (const float4*)(g_coef + (size_t)m0 * NLOG);
        for (int i = tid; i < 128 * NLOG / 4; i += 256) cs4[i] = gc4[i];
    }
    __syncthreads();

    // fused output epilogue
#pragma unroll
    for (int mt = 0; mt < 4; mt++) {
#pragma unroll
        for (int half = 0; half < 2; half++) {
            const int lrow = wm * 64 + mt * 16 + lr + half * 8;
            const int t = m0 + lrow;
            const float* cc = smf + lrow * NLOG;
            float R[16];
#pragma unroll
            for (int i = 0; i < 16; i++) R[i] = cc[8 + i];
            const float hp0 = cc[4], hp1 = cc[5], hp2 = cc[6], hp3 = cc[7];
            const float* xb = x + (size_t)t * KDIM;
            float* ob = out + (size_t)t * KDIM;
#pragma unroll
            for (int nt = 0; nt < 4; nt++) {
                const int col = n0 + wn * 32 + nt * 8 + lc * 2;
                const float f0 = c[mt][nt][half * 2]     + Wb[col];
                const float f1 = c[mt][nt][half * 2 + 1] + Wb[col + 1];
                float2 xv0 = *(const float2*)(xb + col);
                float2 xv1 = *(const float2*)(xb + CN + col);
                float2 xv2 = *(const float2*)(xb + 2 * CN + col);
                float2 xv3 = *(const float2*)(xb + 3 * CN + col);
                const float hps[4] = {hp0, hp1, hp2, hp3};
#pragma unroll
                for (int o = 0; o < 4; o++) {
                    float2 r;
                    r.x = R[o*4]*xv0.x + R[o*4+1]*xv1.x + R[o*4+2]*xv2.x + R[o*4+3]*xv3.x + hps[o]*f0;
                    r.y = R[o*4]*xv0.y + R[o*4+1]*xv1.y + R[o*4+2]*xv2.y + R[o*4+3]*xv3.y + hps[o]*f1;
                    *(float2*)(ob + o * CN + col) = r;
                }
            }
        }
    }
}

extern "C" void kernel_launch(void* const* d_in, const int* in_sizes, int n_in,
                              void* d_out, int out_size) {
    const float* x      = (const float*)d_in[0];
    const float* phi    = (const float*)d_in[1];
    const float* b      = (const float*)d_in[2];
    const float* a_pre  = (const float*)d_in[3];
    const float* a_post = (const float*)d_in[4];
    const float* a_res  = (const float*)d_in[5];
    const float* W      = (const float*)d_in[6];
    const float* Wb     = (const float*)d_in[7];
    float* out = (float*)d_out;

    cudaFuncSetAttribute(k_gemm, cudaFuncAttributeMaxDynamicSharedMemorySize, GEMM_SMEM);

    k_transpose<<<dim3(CN / 32, CN / 32), dim3(32, 8)>>>(W);
    k_coeffs<<<TOK / 16, 128>>>(x, phi, b, a_pre, a_post, a_res);
    k_xin<<<TOK * 2, 256>>>(x);
    k_gemm<<<dim3(CN / 128, TOK / 128), 256, GEMM_SMEM>>>(x, Wb, out);
}

// round 7
// speedup vs baseline: 1.2670x; 1.0103x over previous
#include <cuda_runtime.h>
#include <cstdint>
#include <cstddef>

#define CN  2048
#define TOK 4096
#define KDIM 8192
#define NLOG 24

__device__ float g_xin [TOK * CN];
__device__ float g_wt  [CN * CN];    // W^T, tf32-rounded, [n][k]
__device__ float g_coef[TOK * NLOG];

__device__ __forceinline__ uint32_t smem_u32(const void* p) {
    uint32_t a;
    asm("{ .reg .u64 t; cvta.to.shared.u64 t, %1; cvt.u32.u64 %0, t; }" : "=r"(a) : "l"(p));
    return a;
}
__device__ __forceinline__ float to_tf32(float v) {
    uint32_t r; asm("cvt.rna.tf32.f32 %0, %1;" : "=r"(r) : "f"(v));
    return __uint_as_float(r);
}
__device__ __forceinline__ void cp16(uint32_t s, const float* g) {
    asm volatile("cp.async.cg.shared.global [%0], [%1], 16;" :: "r"(s), "l"(g));
}
__device__ __forceinline__ void ldsm_x4(uint32_t addr, uint32_t& r0, uint32_t& r1,
                                        uint32_t& r2, uint32_t& r3) {
    asm volatile("ldmatrix.sync.aligned.m8n8.x4.shared.b16 {%0,%1,%2,%3}, [%4];"
        : "=r"(r0), "=r"(r1), "=r"(r2), "=r"(r3) : "r"(addr));
}
__device__ __forceinline__ void ldsm_x2(uint32_t addr, uint32_t& r0, uint32_t& r1) {
    asm volatile("ldmatrix.sync.aligned.m8n8.x2.shared.b16 {%0,%1}, [%2];"
        : "=r"(r0), "=r"(r1) : "r"(addr));
}
__device__ __forceinline__ void mma_tf32(float* c, const uint32_t* a, const uint32_t* b) {
    asm volatile(
        "mma.sync.aligned.m16n8k8.row.col.f32.tf32.tf32.f32 "
        "{%0,%1,%2,%3}, {%4,%5,%6,%7}, {%8,%9}, {%0,%1,%2,%3};"
        : "+f"(c[0]), "+f"(c[1]), "+f"(c[2]), "+f"(c[3])
        : "r"(a[0]), "r"(a[1]), "r"(a[2]), "r"(a[3]), "r"(b[0]), "r"(b[1]));
}

// ---------------- K1: W^T (tf32-rounded) ----------------
__global__ void k_transpose(const float* __restrict__ W) {
    __shared__ float t[32][33];
    int bx = blockIdx.x, by = blockIdx.y, tx = threadIdx.x, ty = threadIdx.y;
#pragma unroll
    for (int i = 0; i < 32; i += 8)
        t[ty + i][tx] = W[(size_t)(by * 32 + ty + i) * CN + bx * 32 + tx];
    __syncthreads();
#pragma unroll
    for (int i = 0; i < 32; i += 8)
        g_wt[(size_t)(bx * 32 + ty + i) * CN + by * 32 + tx] = to_tf32(t[tx][ty + i]);
}

// ---------------- K2: logits + gates + sinkhorn (fused) ----------------
#define FINISH_TOKEN(dst, A, rr) do {                                         \
    float L[NLOG];                                                            \
    _Pragma("unroll") for (int j = 0; j < NLOG; j++) L[j] = A[j] * (rr) + bias[j]; \
    _Pragma("unroll") for (int h = 0; h < 4; h++) {                           \
        (dst)[h]     = 1.0f / (1.0f + expf(-ap * L[h])) + 1e-4f;              \
        (dst)[4 + h] = 2.0f / (1.0f + expf(-aq * L[4 + h]));                  \
    }                                                                         \
    float m[16];                                                              \
    _Pragma("unroll") for (int i = 0; i < 16; i++) m[i] = expf(ar * L[8 + i]);\
    _Pragma("unroll") for (int it = 0; it < 8; it++) {                        \
        _Pragma("unroll") for (int o = 0; o < 4; o++) {                       \
            float inv = 1.0f / (m[o*4] + m[o*4+1] + m[o*4+2] + m[o*4+3] + 1e-6f); \
            m[o*4] *= inv; m[o*4+1] *= inv; m[o*4+2] *= inv; m[o*4+3] *= inv; \
        }                                                                     \
        _Pragma("unroll") for (int i = 0; i < 4; i++) {                       \
            float inv = 1.0f / (m[i] + m[4+i] + m[8+i] + m[12+i] + 1e-6f);    \
            m[i] *= inv; m[4+i] *= inv; m[8+i] *= inv; m[12+i] *= inv;        \
        }                                                                     \
    }                                                                         \
    _Pragma("unroll") for (int i = 0; i < 16; i++) (dst)[8 + i] = m[i];       \
} while (0)

__global__ __launch_bounds__(128) void k_coeffs(const float* __restrict__ x,
                                                const float* __restrict__ phi,
                                                const float* __restrict__ bias,
                                                const float* __restrict__ a_pre,
                                                const float* __restrict__ a_post,
                                                const float* __restrict__ a_res) {
    __shared__ float phi_s[256 * 25];
    const int tid = threadIdx.x, lane = tid & 31, w = tid >> 5;
    const int t0 = blockIdx.x * 16 + w * 4;
    float a0[NLOG], a1[NLOG], a2[NLOG], a3[NLOG];
#pragma unroll
    for (int j = 0; j < NLOG; j++) { a0[j] = a1[j] = a2[j] = a3[j] = 0.f; }
    float s0 = 0.f, s1 = 0.f, s2 = 0.f, s3 = 0.f;
    const float* xr0 = x + (size_t)t0 * KDIM;
    const float* xr1 = xr0 + KDIM;
    const float* xr2 = xr1 + KDIM;
    const float* xr3 = xr2 + KDIM;
    for (int kc = 0; kc < KDIM; kc += 256) {
        for (int i = tid; i < 256 * NLOG; i += 128) {
            int k = i / NLOG, j = i - k * NLOG;
            phi_s[k * 25 + j] = phi[(size_t)(kc + k) * NLOG + j];
        }
        __syncthreads();
#pragma unroll 4
        for (int i = 0; i < 8; i++) {
            int kk = i * 32 + lane;
            int k = kc + kk;
            float x0 = xr0[k], x1 = xr1[k], x2 = xr2[k], x3 = xr3[k];
            s0 += x0 * x0; s1 += x1 * x1; s2 += x2 * x2; s3 += x3 * x3;
            const float* pr = &phi_s[kk * 25];
#pragma unroll
            for (int j = 0; j < NLOG; j++) {
                float p = pr[j];
                a0[j] += x0 * p; a1[j] += x1 * p; a2[j] += x2 * p; a3[j] += x3 * p;
            }
        }
        __syncthreads();
    }
#pragma unroll
    for (int off = 16; off > 0; off >>= 1) {
        s0 += __shfl_down_sync(~0u, s0, off); s1 += __shfl_down_sync(~0u, s1, off);
        s2 += __shfl_down_sync(~0u, s2, off); s3 += __shfl_down_sync(~0u, s3, off);
#pragma unroll
        for (int j = 0; j < NLOG; j++) {
            a0[j] += __shfl_down_sync(~0u, a0[j], off);
            a1[j] += __shfl_down_sync(~0u, a1[j], off);
            a2[j] += __shfl_down_sync(~0u, a2[j], off);
            a3[j] += __shfl_down_sync(~0u, a3[j], off);
        }
    }
    if (lane == 0) {
        const float inv = 1.0f / (float)KDIM;
        const float ap = a_pre[0], aq = a_post[0], ar = a_res[0];
        float r0 = rsqrtf(s0 * inv + 1e-6f), r1 = rsqrtf(s1 * inv + 1e-6f);
        float r2 = rsqrtf(s2 * inv + 1e-6f), r3 = rsqrtf(s3 * inv + 1e-6f);
        FINISH_TOKEN(g_coef + (size_t)t0 * NLOG,       a0, r0);
        FINISH_TOKEN(g_coef + (size_t)(t0 + 1) * NLOG, a1, r1);
        FINISH_TOKEN(g_coef + (size_t)(t0 + 2) * NLOG, a2, r2);
        FINISH_TOKEN(g_coef + (size_t)(t0 + 3) * NLOG, a3, r3);
    }
}

// ---------------- K3: x_in (tf32-rounded) ----------------
__global__ __launch_bounds__(256) void k_xin(const float* __restrict__ x) {
    const int t = blockIdx.x >> 1;
    const int c = ((blockIdx.x & 1) * 256 + threadIdx.x) * 4;
    __shared__ float hp[4];
    if (threadIdx.x < 4) hp[threadIdx.x] = g_coef[(size_t)t * NLOG + threadIdx.x];
    __syncthreads();
    const float* xb = x + (size_t)t * KDIM + c;
    float4 v0 = *(const float4*)xb;
    float4 v1 = *(const float4*)(xb + CN);
    float4 v2 = *(const float4*)(xb + 2 * CN);
    float4 v3 = *(const float4*)(xb + 3 * CN);
    float h0 = hp[0], h1 = hp[1], h2 = hp[2], h3 = hp[3];
    float4 s;
    s.x = to_tf32(h0 * v0.x + h1 * v1.x + h2 * v2.x + h3 * v3.x);
    s.y = to_tf32(h0 * v0.y + h1 * v1.y + h2 * v2.y + h3 * v3.y);
    s.z = to_tf32(h0 * v0.z + h1 * v1.z + h2 * v2.z + h3 * v3.z);
    s.w = to_tf32(h0 * v0.w + h1 * v1.w + h2 * v2.w + h3 * v3.w);
    *(float4*)(g_xin + (size_t)t * CN + c) = s;
}

// ---------------- K4: GEMM + fused output ----------------
// smem stage: A [128][36] fl + B [128][36] fl = 9216 floats (36864 B), 3 stages
static constexpr int ST_FLOATS = 9216;
static constexpr int B_OFF     = 4608;
static constexpr uint32_t GEMM_SMEM = 3u * ST_FLOATS * 4u;   // 110592 B
static constexpr int NKCH = CN / 32;                          // 64

__global__ __launch_bounds__(256, 2) void k_gemm(const float* __restrict__ x,
                                                 const float* __restrict__ Wb,
                                                 float* __restrict__ out) {
    extern __shared__ __align__(16) float smf[];
    const uint32_t sbase = smem_u32(smf);
    const int tid = threadIdx.x, lane = tid & 31, wid = tid >> 5;
    const int wm = wid >> 2, wn = wid & 3;          // 2(m) x 4(n) warp grid
    const int m0 = blockIdx.y * 128, n0 = blockIdx.x * 128;
    const int lr = lane >> 2, lc = lane & 3;

    auto load_stage = [&](int kc, int st) {
        const int k0 = kc * 32;
        const uint32_t sa = sbase + (uint32_t)(st * ST_FLOATS) * 4u;
#pragma unroll
        for (int i = 0; i < 4; i++) {
            int seg = tid + 256 * i, r = seg >> 3, cs = seg & 7;
            cp16(sa + (uint32_t)(r * 36 + cs * 4) * 4u,
                 g_xin + (size_t)(m0 + r) * CN + k0 + cs * 4);
        }
        const uint32_t sb = sa + B_OFF * 4u;
#pragma unroll
        for (int i = 0; i < 4; i++) {
            int seg = tid + 256 * i, r = seg >> 3, cs = seg & 7;
            cp16(sb + (uint32_t)(r * 36 + cs * 4) * 4u,
                 g_wt + (size_t)(n0 + r) * CN + k0 + cs * 4);
        }
        asm volatile("cp.async.commit_group;" ::: "memory");
    };

    load_stage(0, 0);
    load_stage(1, 1);

    // lane-dependent ldmatrix offsets (bytes)
    const uint32_t a_lane = (uint32_t)((((lane & 7) | ((lane >> 1) & 8)) * 36 +
                                        ((lane >> 3) & 1) * 4) * 4);
    const uint32_t b_lane = (uint32_t)(((lane & 7) * 36 + ((lane >> 3) & 1) * 4) * 4);

    float c[4][4][4];
#pragma unroll
    for (int i = 0; i < 4; i++)
#pragma unroll
        for (int j = 0; j < 4; j++)
#pragma unroll
            for (int k = 0; k < 4; k++) c[i][j][k] = 0.f;

    for (int kt = 0; kt < NKCH; kt++) {
        asm volatile("cp.async.wait_group 1;" ::: "memory");
        __syncthreads();
        if (kt + 2 < NKCH) load_stage(kt + 2, (kt + 2) % 3);
        else asm volatile("cp.async.commit_group;" ::: "memory");

        const uint32_t sa = sbase + (uint32_t)((kt % 3) * ST_FLOATS) * 4u;
        const uint32_t abase = sa + (uint32_t)(wm * 64 * 36) * 4u + a_lane;
        const uint32_t bbase = sa + (uint32_t)(B_OFF + wn * 32 * 36) * 4u + b_lane;
#pragma unroll
        for (int s = 0; s < 4; s++) {
            uint32_t a4[4][4], b2[4][2];
#pragma unroll
            for (int mt = 0; mt < 4; mt++) {
                uint32_t r0, r1, r2, r3;
                ldsm_x4(abase + (uint32_t)(mt * 16 * 36 * 4 + s * 32), r0, r1, r2, r3);
                a4[mt][0] = r0; a4[mt][1] = r2; a4[mt][2] = r1; a4[mt][3] = r3;
            }
#pragma unroll
            for (int nt = 0; nt < 4; nt++)
                ldsm_x2(bbase + (uint32_t)(nt * 8 * 36 * 4 + s * 32), b2[nt][0], b2[nt][1]);
#pragma unroll
            for (int mt = 0; mt < 4; mt++)
#pragma unroll
                for (int nt = 0; nt < 4; nt++)
                    mma_tf32(c[mt][nt], a4[mt], b2[nt]);
        }
    }

    // stage this CTA's coefs (128 tokens x 24 fl) into smem
    __syncthreads();
    {
        float4* cs4 = (float4*)smf;
        const float4* gc4 = (const float4*)(g_coef + (size_t)m0 * NLOG);
        for (int i = tid; i < 128 * NLOG / 4; i += 256) cs4[i] = gc4[i];
    }
    __syncthreads();

    // fused output epilogue
#pragma unroll
    for (int mt = 0; mt < 4; mt++) {
#pragma unroll
        for (int half = 0; half < 2; half++) {
            const int lrow = wm * 64 + mt * 16 + lr + half * 8;
            const int t = m0 + lrow;
            const float* cc = smf + lrow * NLOG;
            float R[16];
#pragma unroll
            for (int i = 0; i < 16; i++) R[i] = cc[8 + i];
            const float hp0 = cc[4], hp1 = cc[5], hp2 = cc[6], hp3 = cc[7];
            const float* xb = x + (size_t)t * KDIM;
            float* ob = out + (size_t)t * KDIM;
#pragma unroll
            for (int nt = 0; nt < 4; nt++) {
                const int col = n0 + wn * 32 + nt * 8 + lc * 2;
                const float f0 = c[mt][nt][half * 2]     + Wb[col];
                const float f1 = c[mt][nt][half * 2 + 1] + Wb[col + 1];
                float2 xv0 = *(const float2*)(xb + col);
                float2 xv1 = *(const float2*)(xb + CN + col);
                float2 xv2 = *(const float2*)(xb + 2 * CN + col);
                float2 xv3 = *(const float2*)(xb + 3 * CN + col);
                const float hps[4] = {hp0, hp1, hp2, hp3};
#pragma unroll
                for (int o = 0; o < 4; o++) {
                    float2 r;
                    r.x = R[o*4]*xv0.x + R[o*4+1]*xv1.x + R[o*4+2]*xv2.x + R[o*4+3]*xv3.x + hps[o]*f0;
                    r.y = R[o*4]*xv0.y + R[o*4+1]*xv1.y + R[o*4+2]*xv2.y + R[o*4+3]*xv3.y + hps[o]*f1;
                    *(float2*)(ob + o * CN + col) = r;
                }
            }
        }
    }
}

extern "C" void kernel_launch(void* const* d_in, const int* in_sizes, int n_in,
                              void* d_out, int out_size) {
    const float* x      = (const float*)d_in[0];
    const float* phi    = (const float*)d_in[1];
    const float* b      = (const float*)d_in[2];
    const float* a_pre  = (const float*)d_in[3];
    const float* a_post = (const float*)d_in[4];
    const float* a_res  = (const float*)d_in[5];
    const float* W      = (const float*)d_in[6];
    const float* Wb     = (const float*)d_in[7];
    float* out = (float*)d_out;

    cudaFuncSetAttribute(k_gemm, cudaFuncAttributeMaxDynamicSharedMemorySize, GEMM_SMEM);

    k_transpose<<<dim3(CN / 32, CN / 32), dim3(32, 8)>>>(W);
    k_coeffs<<<TOK / 16, 128>>>(x, phi, b, a_pre, a_post, a_res);
    k_xin<<<TOK * 2, 256>>>(x);
    k_gemm<<<dim3(CN / 128, TOK / 128), 256, GEMM_SMEM>>>(x, Wb, out);
}

// round 9
// speedup vs baseline: 1.3991x; 1.1042x over previous
#include <cuda_runtime.h>
#include <cstdint>
#include <cstddef>

#define CN  2048
#define TOK 4096
#define KDIM 8192
#define NLOG 24

__device__ float g_xin [TOK * CN];
__device__ float g_wt  [CN * CN];    // W^T, tf32-rounded, [n][k]
__device__ float g_coef[TOK * NLOG];

__device__ __forceinline__ uint32_t smem_u32(const void* p) {
    uint32_t a;
    asm("{ .reg .u64 t; cvta.to.shared.u64 t, %1; cvt.u32.u64 %0, t; }" : "=r"(a) : "l"(p));
    return a;
}
__device__ __forceinline__ float to_tf32(float v) {
    uint32_t r; asm("cvt.rna.tf32.f32 %0, %1;" : "=r"(r) : "f"(v));
    return __uint_as_float(r);
}
__device__ __forceinline__ void cp16(uint32_t s, const float* g) {
    asm volatile("cp.async.cg.shared.global [%0], [%1], 16;" :: "r"(s), "l"(g));
}
__device__ __forceinline__ void ldsm_x4(uint32_t addr, uint32_t& r0, uint32_t& r1,
                                        uint32_t& r2, uint32_t& r3) {
    asm volatile("ldmatrix.sync.aligned.m8n8.x4.shared.b16 {%0,%1,%2,%3}, [%4];"
        : "=r"(r0), "=r"(r1), "=r"(r2), "=r"(r3) : "r"(addr));
}
__device__ __forceinline__ void ldsm_x2(uint32_t addr, uint32_t& r0, uint32_t& r1) {
    asm volatile("ldmatrix.sync.aligned.m8n8.x2.shared.b16 {%0,%1}, [%2];"
        : "=r"(r0), "=r"(r1) : "r"(addr));
}
__device__ __forceinline__ void mma_tf32(float* c, const uint32_t* a, const uint32_t* b) {
    asm volatile(
        "mma.sync.aligned.m16n8k8.row.col.f32.tf32.tf32.f32 "
        "{%0,%1,%2,%3}, {%4,%5,%6,%7}, {%8,%9}, {%0,%1,%2,%3};"
        : "+f"(c[0]), "+f"(c[1]), "+f"(c[2]), "+f"(c[3])
        : "r"(a[0]), "r"(a[1]), "r"(a[2]), "r"(a[3]), "r"(b[0]), "r"(b[1]));
}

// ---------------- K1: W^T (tf32-rounded) ----------------
__global__ void k_transpose(const float* __restrict__ W) {
    __shared__ float t[32][33];
    int bx = blockIdx.x, by = blockIdx.y, tx = threadIdx.x, ty = threadIdx.y;
#pragma unroll
    for (int i = 0; i < 32; i += 8)
        t[ty + i][tx] = W[(size_t)(by * 32 + ty + i) * CN + bx * 32 + tx];
    __syncthreads();
#pragma unroll
    for (int i = 0; i < 32; i += 8)
        g_wt[(size_t)(bx * 32 + ty + i) * CN + by * 32 + tx] = to_tf32(t[tx][ty + i]);
}

// ---------------- K2: logits + gates + sinkhorn (fused) ----------------
#define FINISH_TOKEN(dst, A, rr) do {                                         \
    float L[NLOG];                                                            \
    _Pragma("unroll") for (int j = 0; j < NLOG; j++) L[j] = A[j] * (rr) + bias[j]; \
    _Pragma("unroll") for (int h = 0; h < 4; h++) {                           \
        (dst)[h]     = 1.0f / (1.0f + expf(-ap * L[h])) + 1e-4f;              \
        (dst)[4 + h] = 2.0f / (1.0f + expf(-aq * L[4 + h]));                  \
    }                                                                         \
    float m[16];                                                              \
    _Pragma("unroll") for (int i = 0; i < 16; i++) m[i] = expf(ar * L[8 + i]);\
    _Pragma("unroll") for (int it = 0; it < 8; it++) {                        \
        _Pragma("unroll") for (int o = 0; o < 4; o++) {                       \
            float inv = 1.0f / (m[o*4] + m[o*4+1] + m[o*4+2] + m[o*4+3] + 1e-6f); \
            m[o*4] *= inv; m[o*4+1] *= inv; m[o*4+2] *= inv; m[o*4+3] *= inv; \
        }                                                                     \
        _Pragma("unroll") for (int i = 0; i < 4; i++) {                       \
            float inv = 1.0f / (m[i] + m[4+i] + m[8+i] + m[12+i] + 1e-6f);    \
            m[i] *= inv; m[4+i] *= inv; m[8+i] *= inv; m[12+i] *= inv;        \
        }                                                                     \
    }                                                                         \
    _Pragma("unroll") for (int i = 0; i < 16; i++) (dst)[8 + i] = m[i];       \
} while (0)

// 256 threads = 8 warps, 4 tokens/warp, 32 tokens/block, grid = TOK/32 = 128
// (one block per SM, 2 warps/SMSP -> FFMA issue saturated; phi smem stage
//  amortized over 8 warps)
__global__ __launch_bounds__(256) void k_coeffs(const float* __restrict__ x,
                                                const float* __restrict__ phi,
                                                const float* __restrict__ bias,
                                                const float* __restrict__ a_pre,
                                                const float* __restrict__ a_post,
                                                const float* __restrict__ a_res) {
    __shared__ float phi_s[256 * 25];
    const int tid = threadIdx.x, lane = tid & 31, w = tid >> 5;
    const int t0 = blockIdx.x * 32 + w * 4;
    float a0[NLOG], a1[NLOG], a2[NLOG], a3[NLOG];
#pragma unroll
    for (int j = 0; j < NLOG; j++) { a0[j] = a1[j] = a2[j] = a3[j] = 0.f; }
    float s0 = 0.f, s1 = 0.f, s2 = 0.f, s3 = 0.f;
    const float* xr0 = x + (size_t)t0 * KDIM;
    const float* xr1 = xr0 + KDIM;
    const float* xr2 = xr1 + KDIM;
    const float* xr3 = xr2 + KDIM;
    for (int kc = 0; kc < KDIM; kc += 256) {
        for (int i = tid; i < 256 * NLOG; i += 256) {
            int k = i / NLOG, j = i - k * NLOG;
            phi_s[k * 25 + j] = phi[(size_t)(kc + k) * NLOG + j];
        }
        __syncthreads();
#pragma unroll 4
        for (int i = 0; i < 8; i++) {
            int kk = i * 32 + lane;
            int k = kc + kk;
            float x0 = xr0[k], x1 = xr1[k], x2 = xr2[k], x3 = xr3[k];
            s0 += x0 * x0; s1 += x1 * x1; s2 += x2 * x2; s3 += x3 * x3;
            const float* pr = &phi_s[kk * 25];
#pragma unroll
            for (int j = 0; j < NLOG; j++) {
                float p = pr[j];
                a0[j] += x0 * p; a1[j] += x1 * p; a2[j] += x2 * p; a3[j] += x3 * p;
            }
        }
        __syncthreads();
    }
#pragma unroll
    for (int off = 16; off > 0; off >>= 1) {
        s0 += __shfl_down_sync(~0u, s0, off); s1 += __shfl_down_sync(~0u, s1, off);
        s2 += __shfl_down_sync(~0u, s2, off); s3 += __shfl_down_sync(~0u, s3, off);
#pragma unroll
        for (int j = 0; j < NLOG; j++) {
            a0[j] += __shfl_down_sync(~0u, a0[j], off);
            a1[j] += __shfl_down_sync(~0u, a1[j], off);
            a2[j] += __shfl_down_sync(~0u, a2[j], off);
            a3[j] += __shfl_down_sync(~0u, a3[j], off);
        }
    }
    if (lane == 0) {
        const float inv = 1.0f / (float)KDIM;
        const float ap = a_pre[0], aq = a_post[0], ar = a_res[0];
        float r0 = rsqrtf(s0 * inv + 1e-6f), r1 = rsqrtf(s1 * inv + 1e-6f);
        float r2 = rsqrtf(s2 * inv + 1e-6f), r3 = rsqrtf(s3 * inv + 1e-6f);
        FINISH_TOKEN(g_coef + (size_t)t0 * NLOG,       a0, r0);
        FINISH_TOKEN(g_coef + (size_t)(t0 + 1) * NLOG, a1, r1);
        FINISH_TOKEN(g_coef + (size_t)(t0 + 2) * NLOG, a2, r2);
        FINISH_TOKEN(g_coef + (size_t)(t0 + 3) * NLOG, a3, r3);
    }
}

// ---------------- K3: x_in (tf32-rounded) ----------------
__global__ __launch_bounds__(256) void k_xin(const float* __restrict__ x) {
    const int t = blockIdx.x >> 1;
    const int c = ((blockIdx.x & 1) * 256 + threadIdx.x) * 4;
    __shared__ float hp[4];
    if (threadIdx.x < 4) hp[threadIdx.x] = g_coef[(size_t)t * NLOG + threadIdx.x];
    __syncthreads();
    const float* xb = x + (size_t)t * KDIM + c;
    float4 v0 = *(const float4*)xb;
    float4 v1 = *(const float4*)(xb + CN);
    float4 v2 = *(const float4*)(xb + 2 * CN);
    float4 v3 = *(const float4*)(xb + 3 * CN);
    float h0 = hp[0], h1 = hp[1], h2 = hp[2], h3 = hp[3];
    float4 s;
    s.x = to_tf32(h0 * v0.x + h1 * v1.x + h2 * v2.x + h3 * v3.x);
    s.y = to_tf32(h0 * v0.y + h1 * v1.y + h2 * v2.y + h3 * v3.y);
    s.z = to_tf32(h0 * v0.z + h1 * v1.z + h2 * v2.z + h3 * v3.z);
    s.w = to_tf32(h0 * v0.w + h1 * v1.w + h2 * v2.w + h3 * v3.w);
    *(float4*)(g_xin + (size_t)t * CN + c) = s;
}

// ---------------- K4: GEMM + fused output ----------------
static constexpr int ST_FLOATS = 9216;
static constexpr int B_OFF     = 4608;
static constexpr uint32_t GEMM_SMEM = 3u * ST_FLOATS * 4u;   // 110592 B
static constexpr int NKCH = CN / 32;                          // 64

__global__ __launch_bounds__(256, 2) void k_gemm(const float* __restrict__ x,
                                                 const float* __restrict__ Wb,
                                                 float* __restrict__ out) {
    extern __shared__ __align__(16) float smf[];
    const uint32_t sbase = smem_u32(smf);
    const int tid = threadIdx.x, lane = tid & 31, wid = tid >> 5;
    const int wm = wid >> 2, wn = wid & 3;
    const int m0 = blockIdx.y * 128, n0 = blockIdx.x * 128;
    const int lr = lane >> 2, lc = lane & 3;

    auto load_stage = [&](int kc, int st) {
        const int k0 = kc * 32;
        const uint32_t sa = sbase + (uint32_t)(st * ST_FLOATS) * 4u;
#pragma unroll
        for (int i = 0; i < 4; i++) {
            int seg = tid + 256 * i, r = seg >> 3, cs = seg & 7;
            cp16(sa + (uint32_t)(r * 36 + cs * 4) * 4u,
                 g_xin + (size_t)(m0 + r) * CN + k0 + cs * 4);
        }
        const uint32_t sb = sa + B_OFF * 4u;
#pragma unroll
        for (int i = 0; i < 4; i++) {
            int seg = tid + 256 * i, r = seg >> 3, cs = seg & 7;
            cp16(sb + (uint32_t)(r * 36 + cs * 4) * 4u,
                 g_wt + (size_t)(n0 + r) * CN + k0 + cs * 4);
        }
        asm volatile("cp.async.commit_group;" ::: "memory");
    };

    load_stage(0, 0);
    load_stage(1, 1);

    const uint32_t a_lane = (uint32_t)((((lane & 7) | ((lane >> 1) & 8)) * 36 +
                                        ((lane >> 3) & 1) * 4) * 4);
    const uint32_t b_lane = (uint32_t)(((lane & 7) * 36 + ((lane >> 3) & 1) * 4) * 4);

    float c[4][4][4];
#pragma unroll
    for (int i = 0; i < 4; i++)
#pragma unroll
        for (int j = 0; j < 4; j++)
#pragma unroll
            for (int k = 0; k < 4; k++) c[i][j][k] = 0.f;

    for (int kt = 0; kt < NKCH; kt++) {
        asm volatile("cp.async.wait_group 1;" ::: "memory");
        __syncthreads();
        if (kt + 2 < NKCH) load_stage(kt + 2, (kt + 2) % 3);
        else asm volatile("cp.async.commit_group;" ::: "memory");

        const uint32_t sa = sbase + (uint32_t)((kt % 3) * ST_FLOATS) * 4u;
        const uint32_t abase = sa + (uint32_t)(wm * 64 * 36) * 4u + a_lane;
        const uint32_t bbase = sa + (uint32_t)(B_OFF + wn * 32 * 36) * 4u + b_lane;
#pragma unroll
        for (int s = 0; s < 4; s++) {
            uint32_t a4[4][4], b2[4][2];
#pragma unroll
            for (int mt = 0; mt < 4; mt++) {
                uint32_t r0, r1, r2, r3;
                ldsm_x4(abase + (uint32_t)(mt * 16 * 36 * 4 + s * 32), r0, r1, r2, r3);
                a4[mt][0] = r0; a4[mt][1] = r2; a4[mt][2] = r1; a4[mt][3] = r3;
            }
#pragma unroll
            for (int nt = 0; nt < 4; nt++)
                ldsm_x2(bbase + (uint32_t)(nt * 8 * 36 * 4 + s * 32), b2[nt][0], b2[nt][1]);
#pragma unroll
            for (int mt = 0; mt < 4; mt++)
#pragma unroll
                for (int nt = 0; nt < 4; nt++)
                    mma_tf32(c[mt][nt], a4[mt], b2[nt]);
        }
    }

    __syncthreads();
    {
        float4* cs4 = (float4*)smf;
        const float4* gc4 = (const float4*)(g_coef + (size_t)m0 * NLOG);
        for (int i = tid; i < 128 * NLOG / 4; i += 256) cs4[i] = gc4[i];
    }
    __syncthreads();

#pragma unroll
    for (int mt = 0; mt < 4; mt++) {
#pragma unroll
        for (int half = 0; half < 2; half++) {
            const int lrow = wm * 64 + mt * 16 + lr + half * 8;
            const int t = m0 + lrow;
            const float* cc = smf + lrow * NLOG;
            float R[16];
#pragma unroll
            for (int i = 0; i < 16; i++) R[i] = cc[8 + i];
            const float hp0 = cc[4], hp1 = cc[5], hp2 = cc[6], hp3 = cc[7];
            const float* xb = x + (size_t)t * KDIM;
            float* ob = out + (size_t)t * KDIM;
#pragma unroll
            for (int nt = 0; nt < 4; nt++) {
                const int col = n0 + wn * 32 + nt * 8 + lc * 2;
                const float f0 = c[mt][nt][half * 2]     + Wb[col];
                const float f1 = c[mt][nt][half * 2 + 1] + Wb[col + 1];
                float2 xv0 = *(const float2*)(xb + col);
                float2 xv1 = *(const float2*)(xb + CN + col);
                float2 xv2 = *(const float2*)(xb + 2 * CN + col);
                float2 xv3 = *(const float2*)(xb + 3 * CN + col);
                const float hps[4] = {hp0, hp1, hp2, hp3};
#pragma unroll
                for (int o = 0; o < 4; o++) {
                    float2 r;
                    r.x = R[o*4]*xv0.x + R[o*4+1]*xv1.x + R[o*4+2]*xv2.x + R[o*4+3]*xv3.x + hps[o]*f0;
                    r.y = R[o*4]*xv0.y + R[o*4+1]*xv1.y + R[o*4+2]*xv2.y + R[o*4+3]*xv3.y + hps[o]*f1;
                    *(float2*)(ob + o * CN + col) = r;
                }
            }
        }
    }
}

extern "C" void kernel_launch(void* const* d_in, const int* in_sizes, int n_in,
                              void* d_out, int out_size) {
    const float* x      = (const float*)d_in[0];
    const float* phi    = (const float*)d_in[1];
    const float* b      = (const float*)d_in[2];
    const float* a_pre  = (const float*)d_in[3];
    const float* a_post = (const float*)d_in[4];
    const float* a_res  = (const float*)d_in[5];
    const float* W      = (const float*)d_in[6];
    const float* Wb     = (const float*)d_in[7];
    float* out = (float*)d_out;

    cudaFuncSetAttribute(k_gemm, cudaFuncAttributeMaxDynamicSharedMemorySize, GEMM_SMEM);

    k_transpose<<<dim3(CN / 32, CN / 32), dim3(32, 8)>>>(W);
    k_coeffs<<<TOK / 32, 256>>>(x, phi, b, a_pre, a_post, a_res);
    k_xin<<<TOK * 2, 256>>>(x);
    k_gemm<<<dim3(CN / 128, TOK / 128), 256, GEMM_SMEM>>>(x, Wb, out);
}

// round 12
// speedup vs baseline: 1.7122x; 1.2238x over previous
#include <cuda_runtime.h>
#include <cstdint>
#include <cstddef>

#define CN  2048
#define TOK 4096
#define KDIM 8192
#define NLOG 24

__device__ float g_xin [TOK * CN];
__device__ float g_wt  [CN * CN];     // W^T, tf32-rounded, [n][k]
__device__ float g_phit[32 * KDIM];   // phi^T, tf32-rounded, rows 24..31 zero
__device__ float g_coef[TOK * NLOG];

__device__ __forceinline__ uint32_t smem_u32(const void* p) {
    uint32_t a;
    asm("{ .reg .u64 t; cvta.to.shared.u64 t, %1; cvt.u32.u64 %0, t; }" : "=r"(a) : "l"(p));
    return a;
}
__device__ __forceinline__ float to_tf32(float v) {
    uint32_t r; asm("cvt.rna.tf32.f32 %0, %1;" : "=r"(r) : "f"(v));
    return __uint_as_float(r);
}
__device__ __forceinline__ void cp16(uint32_t s, const float* g) {
    asm volatile("cp.async.cg.shared.global [%0], [%1], 16;" :: "r"(s), "l"(g));
}
__device__ __forceinline__ void ldsm_x4(uint32_t addr, uint32_t& r0, uint32_t& r1,
                                        uint32_t& r2, uint32_t& r3) {
    asm volatile("ldmatrix.sync.aligned.m8n8.x4.shared.b16 {%0,%1,%2,%3}, [%4];"
        : "=r"(r0), "=r"(r1), "=r"(r2), "=r"(r3) : "r"(addr));
}
__device__ __forceinline__ void ldsm_x2(uint32_t addr, uint32_t& r0, uint32_t& r1) {
    asm volatile("ldmatrix.sync.aligned.m8n8.x2.shared.b16 {%0,%1}, [%2];"
        : "=r"(r0), "=r"(r1) : "r"(addr));
}
__device__ __forceinline__ void mma_tf32(float* c, const uint32_t* a, const uint32_t* b) {
    asm volatile(
        "mma.sync.aligned.m16n8k8.row.col.f32.tf32.tf32.f32 "
        "{%0,%1,%2,%3}, {%4,%5,%6,%7}, {%8,%9}, {%0,%1,%2,%3};"
        : "+f"(c[0]), "+f"(c[1]), "+f"(c[2]), "+f"(c[3])
        : "r"(a[0]), "r"(a[1]), "r"(a[2]), "r"(a[3]), "r"(b[0]), "r"(b[1]));
}

// ---------------- K1: W^T (tf32-rounded) ----------------
__global__ void k_transpose(const float* __restrict__ W) {
    __shared__ float t[32][33];
    int bx = blockIdx.x, by = blockIdx.y, tx = threadIdx.x, ty = threadIdx.y;
#pragma unroll
    for (int i = 0; i < 32; i += 8)
        t[ty + i][tx] = W[(size_t)(by * 32 + ty + i) * CN + bx * 32 + tx];
    __syncthreads();
#pragma unroll
    for (int i = 0; i < 32; i += 8)
        g_wt[(size_t)(bx * 32 + ty + i) * CN + by * 32 + tx] = to_tf32(t[tx][ty + i]);
}

// ---------------- K1b: phi^T (tf32-rounded, padded to 32 rows) ----------------
__global__ void k_phiprep(const float* __restrict__ phi) {
    __shared__ float t[32][25];
    const int k0 = blockIdx.x * 32;
    const int tx = threadIdx.x, ty = threadIdx.y;   // 32 x 8
#pragma unroll
    for (int jj = 0; jj < 3; jj++) {
        int j = ty + jj * 8;
        t[tx][j] = phi[(size_t)(k0 + tx) * NLOG + j];
    }
    __syncthreads();
#pragma unroll
    for (int jj = 0; jj < 4; jj++) {
        int j = ty + jj * 8;
        float v = (j < NLOG) ? to_tf32(t[tx][j]) : 0.f;
        g_phit[(size_t)j * KDIM + k0 + tx] = v;
    }
}

// ---------------- sink helper ----------------
#define FINISH_TOKEN(dst, A, rr) do {                                         \
    float L[NLOG];                                                            \
    _Pragma("unroll") for (int j = 0; j < NLOG; j++) L[j] = A[j] * (rr) + bias[j]; \
    _Pragma("unroll") for (int h = 0; h < 4; h++) {                           \
        (dst)[h]     = 1.0f / (1.0f + expf(-ap * L[h])) + 1e-4f;              \
        (dst)[4 + h] = 2.0f / (1.0f + expf(-aq * L[4 + h]));                  \
    }                                                                         \
    float m[16];                                                              \
    _Pragma("unroll") for (int i = 0; i < 16; i++) m[i] = expf(ar * L[8 + i]);\
    _Pragma("unroll") for (int it = 0; it < 8; it++) {                        \
        _Pragma("unroll") for (int o = 0; o < 4; o++) {                       \
            float inv = 1.0f / (m[o*4] + m[o*4+1] + m[o*4+2] + m[o*4+3] + 1e-6f); \
            m[o*4] *= inv; m[o*4+1] *= inv; m[o*4+2] *= inv; m[o*4+3] *= inv; \
        }                                                                     \
        _Pragma("unroll") for (int i = 0; i < 4; i++) {                       \
            float inv = 1.0f / (m[i] + m[4+i] + m[8+i] + m[12+i] + 1e-6f);    \
            m[i] *= inv; m[4+i] *= inv; m[8+i] *= inv; m[12+i] *= inv;        \
        }                                                                     \
    }                                                                         \
    _Pragma("unroll") for (int i = 0; i < 16; i++) (dst)[8 + i] = m[i];       \
} while (0)

// ---------------- K2: logits via tensor cores + ss + gates + sinkhorn -------
// grid 128, 256 thr. 32 tokens/CTA. logits = (x @ phi)*r + b  (linearity).
__global__ __launch_bounds__(256) void k_logits(const float* __restrict__ x,
                                                const float* __restrict__ bias,
                                                const float* __restrict__ a_pre,
                                                const float* __restrict__ a_post,
                                                const float* __restrict__ a_res) {
    __shared__ __align__(16) float smA[3][1152];   // [32 tok][36]
    __shared__ __align__(16) float smB[3][1152];   // [32 n ][36]
    __shared__ float Lbuf[4][32][25];
    __shared__ float ssm[32];
    const int tid = threadIdx.x, lane = tid & 31, wid = tid >> 5;
    const int mt = wid & 1, kq = wid >> 1;         // 2(m) x 4(k-quarter)
    const int m0 = blockIdx.x * 32;
    const int row = tid >> 3, cs = tid & 7;        // loader mapping
    const float* xrow = x + (size_t)(m0 + row) * KDIM + cs * 4;
    const float* prow = g_phit + (size_t)row * KDIM + cs * 4;
    const uint32_t dstoff = (uint32_t)(row * 36 + cs * 4) * 4u;

    auto load_stage = [&](int kc, int st) {
        cp16(smem_u32(smA[st]) + dstoff, xrow + kc * 32);
        cp16(smem_u32(smB[st]) + dstoff, prow + kc * 32);
        asm volatile("cp.async.commit_group;" ::: "memory");
    };

    load_stage(0, 0);
    load_stage(1, 1);

    const uint32_t a_lane = (uint32_t)((((lane & 7) | ((lane >> 1) & 8)) * 36 +
                                        ((lane >> 3) & 1) * 4) * 4);
    const uint32_t b_lane = (uint32_t)(((lane & 7) * 36 + ((lane >> 3) & 1) * 4) * 4);

    float c[3][4];
#pragma unroll
    for (int i = 0; i < 3; i++)
#pragma unroll
        for (int j = 0; j < 4; j++) c[i][j] = 0.f;
    float ss = 0.f;

    for (int kt = 0; kt < KDIM / 32; kt++) {
        const int st = kt % 3;
        asm volatile("cp.async.wait_group 1;" ::: "memory");
        __syncthreads();
        // fix pass: round A in place to tf32 (rna) + exact fp32 sum of squares
        {
            float4* p = (float4*)(smA[st] + row * 36 + cs * 4);
            float4 v = *p;
            ss += v.x * v.x + v.y * v.y + v.z * v.z + v.w * v.w;
            v.x = to_tf32(v.x); v.y = to_tf32(v.y); v.z = to_tf32(v.z); v.w = to_tf32(v.w);
            *p = v;
        }
        __syncthreads();
        if (kt + 2 < KDIM / 32) load_stage(kt + 2, (kt + 2) % 3);
        else asm volatile("cp.async.commit_group;" ::: "memory");

        const uint32_t abase = smem_u32(smA[st]) + (uint32_t)(mt * 16 * 36) * 4u +
                               a_lane + (uint32_t)(kq * 32);
        const uint32_t bbase = smem_u32(smB[st]) + b_lane + (uint32_t)(kq * 32);
        uint32_t a4[4], b2[3][2];
        {
            uint32_t r0, r1, r2, r3;
            ldsm_x4(abase, r0, r1, r2, r3);
            a4[0] = r0; a4[1] = r2; a4[2] = r1; a4[3] = r3;
        }
#pragma unroll
        for (int nt = 0; nt < 3; nt++)
            ldsm_x2(bbase + (uint32_t)(nt * 8 * 36 * 4), b2[nt][0], b2[nt][1]);
#pragma unroll
        for (int nt = 0; nt < 3; nt++)
            mma_tf32(c[nt], a4, b2[nt]);
    }

    // ss reduce within 8-thread row groups (consecutive lanes)
    ss += __shfl_down_sync(~0u, ss, 4);
    ss += __shfl_down_sync(~0u, ss, 2);
    ss += __shfl_down_sync(~0u, ss, 1);
    if (cs == 0) ssm[row] = ss;

    // dump partial accumulators
    {
        const int lr = lane >> 2, lc = lane & 3;
#pragma unroll
        for (int nt = 0; nt < 3; nt++) {
            Lbuf[kq][mt * 16 + lr][nt * 8 + lc * 2]         = c[nt][0];
            Lbuf[kq][mt * 16 + lr][nt * 8 + lc * 2 + 1]     = c[nt][1];
            Lbuf[kq][mt * 16 + lr + 8][nt * 8 + lc * 2]     = c[nt][2];
            Lbuf[kq][mt * 16 + lr + 8][nt * 8 + lc * 2 + 1] = c[nt][3];
        }
    }
    __syncthreads();

    if (tid < 32) {
        float A[NLOG];
#pragma unroll
        for (int j = 0; j < NLOG; j++)
            A[j] = Lbuf[0][tid][j] + Lbuf[1][tid][j] + Lbuf[2][tid][j] + Lbuf[3][tid][j];
        const float ap = a_pre[0], aq = a_post[0], ar = a_res[0];
        const float r = rsqrtf(ssm[tid] * (1.0f / (float)KDIM) + 1e-6f);
        FINISH_TOKEN(g_coef + (size_t)(m0 + tid) * NLOG, A, r);
    }
}

// ---------------- K3: x_in (tf32-rounded) ----------------
__global__ __launch_bounds__(256) void k_xin(const float* __restrict__ x) {
    const int t = blockIdx.x >> 1;
    const int c = ((blockIdx.x & 1) * 256 + threadIdx.x) * 4;
    __shared__ float hp[4];
    if (threadIdx.x < 4) hp[threadIdx.x] = g_coef[(size_t)t * NLOG + threadIdx.x];
    __syncthreads();
    const float* xb = x + (size_t)t * KDIM + c;
    float4 v0 = *(const float4*)xb;
    float4 v1 = *(const float4*)(xb + CN);
    float4 v2 = *(const float4*)(xb + 2 * CN);
    float4 v3 = *(const float4*)(xb + 3 * CN);
    float h0 = hp[0], h1 = hp[1], h2 = hp[2], h3 = hp[3];
    float4 s;
    s.x = to_tf32(h0 * v0.x + h1 * v1.x + h2 * v2.x + h3 * v3.x);
    s.y = to_tf32(h0 * v0.y + h1 * v1.y + h2 * v2.y + h3 * v3.y);
    s.z = to_tf32(h0 * v0.z + h1 * v1.z + h2 * v2.z + h3 * v3.z);
    s.w = to_tf32(h0 * v0.w + h1 * v1.w + h2 * v2.w + h3 * v3.w);
    *(float4*)(g_xin + (size_t)t * CN + c) = s;
}

// ---------------- K4: GEMM + fused output ----------------
static constexpr int ST_FLOATS = 9216;
static constexpr int B_OFF     = 4608;
static constexpr uint32_t GEMM_SMEM = 3u * ST_FLOATS * 4u;   // 110592 B
static constexpr int NKCH = CN / 32;

__global__ __launch_bounds__(256, 2) void k_gemm(const float* __restrict__ x,
                                                 const float* __restrict__ Wb,
                                                 float* __restrict__ out) {
    extern __shared__ __align__(16) float smf[];
    const uint32_t sbase = smem_u32(smf);
    const int tid = threadIdx.x, lane = tid & 31, wid = tid >> 5;
    const int wm = wid >> 2, wn = wid & 3;
    const int m0 = blockIdx.y * 128, n0 = blockIdx.x * 128;
    const int lr = lane >> 2, lc = lane & 3;

    auto load_stage = [&](int kc, int st) {
        const int k0 = kc * 32;
        const uint32_t sa = sbase + (uint32_t)(st * ST_FLOATS) * 4u;
#pragma unroll
        for (int i = 0; i < 4; i++) {
            int seg = tid + 256 * i, r = seg >> 3, cs = seg & 7;
            cp16(sa + (uint32_t)(r * 36 + cs * 4) * 4u,
                 g_xin + (size_t)(m0 + r) * CN + k0 + cs * 4);
        }
        const uint32_t sb = sa + B_OFF * 4u;
#pragma unroll
        for (int i = 0; i < 4; i++) {
            int seg = tid + 256 * i, r = seg >> 3, cs = seg & 7;
            cp16(sb + (uint32_t)(r * 36 + cs * 4) * 4u,
                 g_wt + (size_t)(n0 + r) * CN + k0 + cs * 4);
        }
        asm volatile("cp.async.commit_group;" ::: "memory");
    };

    load_stage(0, 0);
    load_stage(1, 1);

    const uint32_t a_lane = (uint32_t)((((lane & 7) | ((lane >> 1) & 8)) * 36 +
                                        ((lane >> 3) & 1) * 4) * 4);
    const uint32_t b_lane = (uint32_t)(((lane & 7) * 36 + ((lane >> 3) & 1) * 4) * 4);

    float c[4][4][4];
#pragma unroll
    for (int i = 0; i < 4; i++)
#pragma unroll
        for (int j = 0; j < 4; j++)
#pragma unroll
            for (int k = 0; k < 4; k++) c[i][j][k] = 0.f;

    for (int kt = 0; kt < NKCH; kt++) {
        asm volatile("cp.async.wait_group 1;" ::: "memory");
        __syncthreads();
        if (kt + 2 < NKCH) load_stage(kt + 2, (kt + 2) % 3);
        else asm volatile("cp.async.commit_group;" ::: "memory");

        const uint32_t sa = sbase + (uint32_t)((kt % 3) * ST_FLOATS) * 4u;
        const uint32_t abase = sa + (uint32_t)(wm * 64 * 36) * 4u + a_lane;
        const uint32_t bbase = sa + (uint32_t)(B_OFF + wn * 32 * 36) * 4u + b_lane;
#pragma unroll
        for (int s = 0; s < 4; s++) {
            uint32_t a4[4][4], b2[4][2];
#pragma unroll
            for (int mt = 0; mt < 4; mt++) {
                uint32_t r0, r1, r2, r3;
                ldsm_x4(abase + (uint32_t)(mt * 16 * 36 * 4 + s * 32), r0, r1, r2, r3);
                a4[mt][0] = r0; a4[mt][1] = r2; a4[mt][2] = r1; a4[mt][3] = r3;
            }
#pragma unroll
            for (int nt = 0; nt < 4; nt++)
                ldsm_x2(bbase + (uint32_t)(nt * 8 * 36 * 4 + s * 32), b2[nt][0], b2[nt][1]);
#pragma unroll
            for (int mt = 0; mt < 4; mt++)
#pragma unroll
                for (int nt = 0; nt < 4; nt++)
                    mma_tf32(c[mt][nt], a4[mt], b2[nt]);
        }
    }

    __syncthreads();
    {
        float4* cs4 = (float4*)smf;
        const float4* gc4 = (const float4*)(g_coef + (size_t)m0 * NLOG);
        for (int i = tid; i < 128 * NLOG / 4; i += 256) cs4[i] = gc4[i];
    }
    __syncthreads();

#pragma unroll
    for (int mt = 0; mt < 4; mt++) {
#pragma unroll
        for (int half = 0; half < 2; half++) {
            const int lrow = wm * 64 + mt * 16 + lr + half * 8;
            const int t = m0 + lrow;
            const float* cc = smf + lrow * NLOG;
            float R[16];
#pragma unroll
            for (int i = 0; i < 16; i++) R[i] = cc[8 + i];
            const float hp0 = cc[4], hp1 = cc[5], hp2 = cc[6], hp3 = cc[7];
            const float* xb = x + (size_t)t * KDIM;
            float* ob = out + (size_t)t * KDIM;
#pragma unroll
            for (int nt = 0; nt < 4; nt++) {
                const int col = n0 + wn * 32 + nt * 8 + lc * 2;
                const float f0 = c[mt][nt][half * 2]     + Wb[col];
                const float f1 = c[mt][nt][half * 2 + 1] + Wb[col + 1];
                float2 xv0 = *(const float2*)(xb + col);
                float2 xv1 = *(const float2*)(xb + CN + col);
                float2 xv2 = *(const float2*)(xb + 2 * CN + col);
                float2 xv3 = *(const float2*)(xb + 3 * CN + col);
                const float hps[4] = {hp0, hp1, hp2, hp3};
#pragma unroll
                for (int o = 0; o < 4; o++) {
                    float2 r;
                    r.x = R[o*4]*xv0.x + R[o*4+1]*xv1.x + R[o*4+2]*xv2.x + R[o*4+3]*xv3.x + hps[o]*f0;
                    r.y = R[o*4]*xv0.y + R[o*4+1]*xv1.y + R[o*4+2]*xv2.y + R[o*4+3]*xv3.y + hps[o]*f1;
                    *(float2*)(ob + o * CN + col) = r;
                }
            }
        }
    }
}

extern "C" void kernel_launch(void* const* d_in, const int* in_sizes, int n_in,
                              void* d_out, int out_size) {
    const float* x      = (const float*)d_in[0];
    const float* phi    = (const float*)d_in[1];
    const float* b      = (const float*)d_in[2];
    const float* a_pre  = (const float*)d_in[3];
    const float* a_post = (const float*)d_in[4];
    const float* a_res  = (const float*)d_in[5];
    const float* W      = (const float*)d_in[6];
    const float* Wb     = (const float*)d_in[7];
    float* out = (float*)d_out;

    cudaFuncSetAttribute(k_gemm, cudaFuncAttributeMaxDynamicSharedMemorySize, GEMM_SMEM);

    k_transpose<<<dim3(CN / 32, CN / 32), dim3(32, 8)>>>(W);
    k_phiprep<<<KDIM / 32, dim3(32, 8)>>>(phi);
    k_logits<<<TOK / 32, 256>>>(x, b, a_pre, a_post, a_res);
    k_xin<<<TOK * 2, 256>>>(x);
    k_gemm<<<dim3(CN / 128, TOK / 128), 256, GEMM_SMEM>>>(x, Wb, out);
}

// round 14
// speedup vs baseline: 1.9884x; 1.1613x over previous
#include <cuda_runtime.h>
#include <cstdint>
#include <cstddef>

#define CN  2048
#define TOK 4096
#define KDIM 8192
#define NLOG 24

__device__ float g_xin [TOK * CN];
__device__ float g_wt  [CN * CN];     // W^T, tf32-rounded, [n][k]
__device__ float g_phit[32 * KDIM];   // phi^T, tf32-rounded, rows 24..31 zero
__device__ float g_coef[TOK * NLOG];

__device__ __forceinline__ uint32_t smem_u32(const void* p) {
    uint32_t a;
    asm("{ .reg .u64 t; cvta.to.shared.u64 t, %1; cvt.u32.u64 %0, t; }" : "=r"(a) : "l"(p));
    return a;
}
__device__ __forceinline__ float to_tf32(float v) {
    uint32_t r; asm("cvt.rna.tf32.f32 %0, %1;" : "=r"(r) : "f"(v));
    return __uint_as_float(r);
}
__device__ __forceinline__ void cp16(uint32_t s, const float* g) {
    asm volatile("cp.async.cg.shared.global [%0], [%1], 16;" :: "r"(s), "l"(g));
}
__device__ __forceinline__ void ldsm_x4(uint32_t addr, uint32_t& r0, uint32_t& r1,
                                        uint32_t& r2, uint32_t& r3) {
    asm volatile("ldmatrix.sync.aligned.m8n8.x4.shared.b16 {%0,%1,%2,%3}, [%4];"
        : "=r"(r0), "=r"(r1), "=r"(r2), "=r"(r3) : "r"(addr));
}
__device__ __forceinline__ void ldsm_x2(uint32_t addr, uint32_t& r0, uint32_t& r1) {
    asm volatile("ldmatrix.sync.aligned.m8n8.x2.shared.b16 {%0,%1}, [%2];"
        : "=r"(r0), "=r"(r1) : "r"(addr));
}
__device__ __forceinline__ void mma_tf32(float* c, const uint32_t* a, const uint32_t* b) {
    asm volatile(
        "mma.sync.aligned.m16n8k8.row.col.f32.tf32.tf32.f32 "
        "{%0,%1,%2,%3}, {%4,%5,%6,%7}, {%8,%9}, {%0,%1,%2,%3};"
        : "+f"(c[0]), "+f"(c[1]), "+f"(c[2]), "+f"(c[3])
        : "r"(a[0]), "r"(a[1]), "r"(a[2]), "r"(a[3]), "r"(b[0]), "r"(b[1]));
}

// ---------------- K1: W^T (tf32-rounded) ----------------
__global__ void k_transpose(const float* __restrict__ W) {
    __shared__ float t[32][33];
    int bx = blockIdx.x, by = blockIdx.y, tx = threadIdx.x, ty = threadIdx.y;
#pragma unroll
    for (int i = 0; i < 32; i += 8)
        t[ty + i][tx] = W[(size_t)(by * 32 + ty + i) * CN + bx * 32 + tx];
    __syncthreads();
#pragma unroll
    for (int i = 0; i < 32; i += 8)
        g_wt[(size_t)(bx * 32 + ty + i) * CN + by * 32 + tx] = to_tf32(t[tx][ty + i]);
}

// ---------------- K1b: phi^T (tf32-rounded, padded to 32 rows) ----------------
__global__ void k_phiprep(const float* __restrict__ phi) {
    __shared__ float t[32][25];
    const int k0 = blockIdx.x * 32;
    const int tx = threadIdx.x, ty = threadIdx.y;   // 32 x 8
#pragma unroll
    for (int jj = 0; jj < 3; jj++) {
        int j = ty + jj * 8;
        t[tx][j] = phi[(size_t)(k0 + tx) * NLOG + j];
    }
    __syncthreads();
#pragma unroll
    for (int jj = 0; jj < 4; jj++) {
        int j = ty + jj * 8;
        float v = (j < NLOG) ? to_tf32(t[tx][j]) : 0.f;
        g_phit[(size_t)j * KDIM + k0 + tx] = v;
    }
}

// ---------------- sink helper ----------------
#define FINISH_TOKEN(dst, A, rr) do {                                         \
    float L[NLOG];                                                            \
    _Pragma("unroll") for (int j = 0; j < NLOG; j++) L[j] = A[j] * (rr) + bias[j]; \
    _Pragma("unroll") for (int h = 0; h < 4; h++) {                           \
        (dst)[h]     = 1.0f / (1.0f + expf(-ap * L[h])) + 1e-4f;              \
        (dst)[4 + h] = 2.0f / (1.0f + expf(-aq * L[4 + h]));                  \
    }                                                                         \
    float m[16];                                                              \
    _Pragma("unroll") for (int i = 0; i < 16; i++) m[i] = expf(ar * L[8 + i]);\
    _Pragma("unroll") for (int it = 0; it < 8; it++) {                        \
        _Pragma("unroll") for (int o = 0; o < 4; o++) {                       \
            float inv = 1.0f / (m[o*4] + m[o*4+1] + m[o*4+2] + m[o*4+3] + 1e-6f); \
            m[o*4] *= inv; m[o*4+1] *= inv; m[o*4+2] *= inv; m[o*4+3] *= inv; \
        }                                                                     \
        _Pragma("unroll") for (int i = 0; i < 4; i++) {                       \
            float inv = 1.0f / (m[i] + m[4+i] + m[8+i] + m[12+i] + 1e-6f);    \
            m[i] *= inv; m[4+i] *= inv; m[8+i] *= inv; m[12+i] *= inv;        \
        }                                                                     \
    }                                                                         \
    _Pragma("unroll") for (int i = 0; i < 16; i++) (dst)[8 + i] = m[i];       \
} while (0)

// ---------------- K2: logits via tensor cores (wide 128-k stages) -----------
static constexpr int LG_ROW   = 132;                 // floats/row (128 + 4 pad)
static constexpr int LG_STF   = 32 * LG_ROW;         // 4224 floats per operand
static constexpr int LG_STAGE = 2 * LG_STF;          // A + B
static constexpr uint32_t LG_SMEM = 3u * LG_STAGE * 4u;  // 101376 B
static constexpr int LG_NKT = KDIM / 128;            // 64

__global__ __launch_bounds__(256) void k_logits(const float* __restrict__ x,
                                                const float* __restrict__ bias,
                                                const float* __restrict__ a_pre,
                                                const float* __restrict__ a_post,
                                                const float* __restrict__ a_res) {
    extern __shared__ __align__(16) float lsm[];
    __shared__ float Lbuf[4][32][25];
    __shared__ float ssm[32];
    const int tid = threadIdx.x, lane = tid & 31, wid = tid >> 5;
    const int mt = wid & 1, kq = wid >> 1;           // 2(m) x 4(k-quarter)
    const int m0 = blockIdx.x * 32;
    const int row = tid >> 3, cs = tid & 7;
    const float* xrow = x + (size_t)(m0 + row) * KDIM + cs * 4;
    const float* prow = g_phit + (size_t)row * KDIM + cs * 4;

    auto load_stage = [&](int kc, int st) {
        float* A = lsm + st * LG_STAGE;
        float* B = A + LG_STF;
#pragma unroll
        for (int i = 0; i < 4; i++) {
            cp16(smem_u32(A + row * LG_ROW + i * 32 + cs * 4), xrow + kc * 128 + i * 32);
            cp16(smem_u32(B + row * LG_ROW + i * 32 + cs * 4), prow + kc * 128 + i * 32);
        }
        asm volatile("cp.async.commit_group;" ::: "memory");
    };

    load_stage(0, 0);
    load_stage(1, 1);

    const uint32_t a_lane = (uint32_t)((((lane & 7) | ((lane >> 1) & 8)) * LG_ROW +
                                        ((lane >> 3) & 1) * 4) * 4);
    const uint32_t b_lane = (uint32_t)(((lane & 7) * LG_ROW + ((lane >> 3) & 1) * 4) * 4);

    float c[3][4];
#pragma unroll
    for (int i = 0; i < 3; i++)
#pragma unroll
        for (int j = 0; j < 4; j++) c[i][j] = 0.f;
    float ss = 0.f;

    for (int kt = 0; kt < LG_NKT; kt++) {
        const int st = kt % 3;
        float* A = lsm + st * LG_STAGE;
        asm volatile("cp.async.wait_group 1;" ::: "memory");
        __syncthreads();
        // fix pass: round A in place to tf32 (rna) + exact fp32 sum of squares
#pragma unroll
        for (int i = 0; i < 4; i++) {
            float4* p = (float4*)(A + row * LG_ROW + i * 32 + cs * 4);
            float4 v = *p;
            ss += v.x * v.x + v.y * v.y + v.z * v.z + v.w * v.w;
            v.x = to_tf32(v.x); v.y = to_tf32(v.y); v.z = to_tf32(v.z); v.w = to_tf32(v.w);
            *p = v;
        }
        __syncthreads();
        if (kt + 2 < LG_NKT) load_stage(kt + 2, (kt + 2) % 3);
        else asm volatile("cp.async.commit_group;" ::: "memory");

        const uint32_t Abase = smem_u32(A) + (uint32_t)(mt * 16 * LG_ROW) * 4u + a_lane +
                               (uint32_t)(kq * 32 * 4);
        const uint32_t Bbase = smem_u32(A + LG_STF) + b_lane + (uint32_t)(kq * 32 * 4);
#pragma unroll
        for (int s = 0; s < 4; s++) {
            uint32_t a4[4], b2[3][2];
            {
                uint32_t r0, r1, r2, r3;
                ldsm_x4(Abase + (uint32_t)(s * 32), r0, r1, r2, r3);
                a4[0] = r0; a4[1] = r2; a4[2] = r1; a4[3] = r3;
            }
#pragma unroll
            for (int nt = 0; nt < 3; nt++)
                ldsm_x2(Bbase + (uint32_t)(nt * 8 * LG_ROW * 4 + s * 32), b2[nt][0], b2[nt][1]);
#pragma unroll
            for (int nt = 0; nt < 3; nt++)
                mma_tf32(c[nt], a4, b2[nt]);
        }
    }

    // ss reduce within 8-thread row groups
    ss += __shfl_down_sync(~0u, ss, 4);
    ss += __shfl_down_sync(~0u, ss, 2);
    ss += __shfl_down_sync(~0u, ss, 1);
    if (cs == 0) ssm[row] = ss;

    {
        const int lr = lane >> 2, lc = lane & 3;
#pragma unroll
        for (int nt = 0; nt < 3; nt++) {
            Lbuf[kq][mt * 16 + lr][nt * 8 + lc * 2]         = c[nt][0];
            Lbuf[kq][mt * 16 + lr][nt * 8 + lc * 2 + 1]     = c[nt][1];
            Lbuf[kq][mt * 16 + lr + 8][nt * 8 + lc * 2]     = c[nt][2];
            Lbuf[kq][mt * 16 + lr + 8][nt * 8 + lc * 2 + 1] = c[nt][3];
        }
    }
    __syncthreads();

    if (tid < 32) {
        float A[NLOG];
#pragma unroll
        for (int j = 0; j < NLOG; j++)
            A[j] = Lbuf[0][tid][j] + Lbuf[1][tid][j] + Lbuf[2][tid][j] + Lbuf[3][tid][j];
        const float ap = a_pre[0], aq = a_post[0], ar = a_res[0];
        const float r = rsqrtf(ssm[tid] * (1.0f / (float)KDIM) + 1e-6f);
        FINISH_TOKEN(g_coef + (size_t)(m0 + tid) * NLOG, A, r);
    }
}

// ---------------- K3: x_in (tf32-rounded) ----------------
__global__ __launch_bounds__(256) void k_xin(const float* __restrict__ x) {
    const int t = blockIdx.x >> 1;
    const int c = ((blockIdx.x & 1) * 256 + threadIdx.x) * 4;
    __shared__ float hp[4];
    if (threadIdx.x < 4) hp[threadIdx.x] = g_coef[(size_t)t * NLOG + threadIdx.x];
    __syncthreads();
    const float* xb = x + (size_t)t * KDIM + c;
    float4 v0 = *(const float4*)xb;
    float4 v1 = *(const float4*)(xb + CN);
    float4 v2 = *(const float4*)(xb + 2 * CN);
    float4 v3 = *(const float4*)(xb + 3 * CN);
    float h0 = hp[0], h1 = hp[1], h2 = hp[2], h3 = hp[3];
    float4 s;
    s.x = to_tf32(h0 * v0.x + h1 * v1.x + h2 * v2.x + h3 * v3.x);
    s.y = to_tf32(h0 * v0.y + h1 * v1.y + h2 * v2.y + h3 * v3.y);
    s.z = to_tf32(h0 * v0.z + h1 * v1.z + h2 * v2.z + h3 * v3.z);
    s.w = to_tf32(h0 * v0.w + h1 * v1.w + h2 * v2.w + h3 * v3.w);
    *(float4*)(g_xin + (size_t)t * CN + c) = s;
}

// ---------------- K4: GEMM + fused output ----------------
static constexpr int ST_FLOATS = 9216;
static constexpr int B_OFF     = 4608;
static constexpr uint32_t GEMM_SMEM = 3u * ST_FLOATS * 4u;   // 110592 B
static constexpr int NKCH = CN / 32;

__global__ __launch_bounds__(256, 2) void k_gemm(const float* __restrict__ x,
                                                 const float* __restrict__ Wb,
                                                 float* __restrict__ out) {
    extern __shared__ __align__(16) float smf[];
    const uint32_t sbase = smem_u32(smf);
    const int tid = threadIdx.x, lane = tid & 31, wid = tid >> 5;
    const int wm = wid >> 2, wn = wid & 3;
    const int srot = wid & 3;                       // de-burst rotation
    const int m0 = blockIdx.y * 128, n0 = blockIdx.x * 128;
    const int lr = lane >> 2, lc = lane & 3;

    auto load_stage = [&](int kc, int st) {
        const int k0 = kc * 32;
        const uint32_t sa = sbase + (uint32_t)(st * ST_FLOATS) * 4u;
#pragma unroll
        for (int i = 0; i < 4; i++) {
            int seg = tid + 256 * i, r = seg >> 3, cs = seg & 7;
            cp16(sa + (uint32_t)(r * 36 + cs * 4) * 4u,
                 g_xin + (size_t)(m0 + r) * CN + k0 + cs * 4);
        }
        const uint32_t sb = sa + B_OFF * 4u;
#pragma unroll
        for (int i = 0; i < 4; i++) {
            int seg = tid + 256 * i, r = seg >> 3, cs = seg & 7;
            cp16(sb + (uint32_t)(r * 36 + cs * 4) * 4u,
                 g_wt + (size_t)(n0 + r) * CN + k0 + cs * 4);
        }
        asm volatile("cp.async.commit_group;" ::: "memory");
    };

    load_stage(0, 0);
    load_stage(1, 1);

    const uint32_t a_lane = (uint32_t)((((lane & 7) | ((lane >> 1) & 8)) * 36 +
                                        ((lane >> 3) & 1) * 4) * 4);
    // x4 B: lanes 0-15 -> first 8-row block, lanes 16-31 -> next 8-row block
    const uint32_t b_lane4 = (uint32_t)(((lane & 7) * 36 + ((lane >> 3) & 1) * 4 +
                                         ((lane >> 4) & 1) * (8 * 36)) * 4);

    float c[4][4][4];
#pragma unroll
    for (int i = 0; i < 4; i++)
#pragma unroll
        for (int j = 0; j < 4; j++)
#pragma unroll
            for (int k = 0; k < 4; k++) c[i][j][k] = 0.f;

    for (int kt = 0; kt < NKCH; kt++) {
        asm volatile("cp.async.wait_group 1;" ::: "memory");
        __syncthreads();
        if (kt + 2 < NKCH) load_stage(kt + 2, (kt + 2) % 3);
        else asm volatile("cp.async.commit_group;" ::: "memory");

        const uint32_t sa = sbase + (uint32_t)((kt % 3) * ST_FLOATS) * 4u;
        const uint32_t abase = sa + (uint32_t)(wm * 64 * 36) * 4u + a_lane;
        const uint32_t bbase = sa + (uint32_t)(B_OFF + wn * 32 * 36) * 4u + b_lane4;
#pragma unroll
        for (int s0 = 0; s0 < 4; s0++) {
            const int s = (s0 + srot) & 3;          // per-warp phase shift
            uint32_t a4[4][4], b2[4][2];
#pragma unroll
            for (int mt = 0; mt < 4; mt++) {
                uint32_t r0, r1, r2, r3;
                ldsm_x4(abase + (uint32_t)(mt * 16 * 36 * 4 + s * 32), r0, r1, r2, r3);
                a4[mt][0] = r0; a4[mt][1] = r2; a4[mt][2] = r1; a4[mt][3] = r3;
            }
#pragma unroll
            for (int p = 0; p < 2; p++) {
                uint32_t r0, r1, r2, r3;
                ldsm_x4(bbase + (uint32_t)(p * 16 * 36 * 4 + s * 32), r0, r1, r2, r3);
                b2[2 * p][0] = r0; b2[2 * p][1] = r1;
                b2[2 * p + 1][0] = r2; b2[2 * p + 1][1] = r3;
            }
#pragma unroll
            for (int mt = 0; mt < 4; mt++)
#pragma unroll
                for (int nt = 0; nt < 4; nt++)
                    mma_tf32(c[mt][nt], a4[mt], b2[nt]);
        }
    }

    __syncthreads();
    {
        float4* cs4 = (float4*)smf;
        const float4* gc4 = (const float4*)(g_coef + (size_t)m0 * NLOG);
        for (int i = tid; i < 128 * NLOG / 4; i += 256) cs4[i] = gc4[i];
    }
    __syncthreads();

#pragma unroll
    for (int mt = 0; mt < 4; mt++) {
#pragma unroll
        for (int half = 0; half < 2; half++) {
            const int lrow = wm * 64 + mt * 16 + lr + half * 8;
            const int t = m0 + lrow;
            const float* cc = smf + lrow * NLOG;
            float R[16];
#pragma unroll
            for (int i = 0; i < 16; i++) R[i] = cc[8 + i];
            const float hp0 = cc[4], hp1 = cc[5], hp2 = cc[6], hp3 = cc[7];
            const float* xb = x + (size_t)t * KDIM;
            float* ob = out + (size_t)t * KDIM;
#pragma unroll
            for (int nt = 0; nt < 4; nt++) {
                const int col = n0 + wn * 32 + nt * 8 + lc * 2;
                const float f0 = c[mt][nt][half * 2]     + Wb[col];
                const float f1 = c[mt][nt][half * 2 + 1] + Wb[col + 1];
                float2 xv0 = *(const float2*)(xb + col);
                float2 xv1 = *(const float2*)(xb + CN + col);
                float2 xv2 = *(const float2*)(xb + 2 * CN + col);
                float2 xv3 = *(const float2*)(xb + 3 * CN + col);
                const float hps[4] = {hp0, hp1, hp2, hp3};
#pragma unroll
                for (int o = 0; o < 4; o++) {
                    float2 r;
                    r.x = R[o*4]*xv0.x + R[o*4+1]*xv1.x + R[o*4+2]*xv2.x + R[o*4+3]*xv3.x + hps[o]*f0;
                    r.y = R[o*4]*xv0.y + R[o*4+1]*xv1.y + R[o*4+2]*xv2.y + R[o*4+3]*xv3.y + hps[o]*f1;
                    *(float2*)(ob + o * CN + col) = r;
                }
            }
        }
    }
}

extern "C" void kernel_launch(void* const* d_in, const int* in_sizes, int n_in,
                              void* d_out, int out_size) {
    const float* x      = (const float*)d_in[0];
    const float* phi    = (const float*)d_in[1];
    const float* b      = (const float*)d_in[2];
    const float* a_pre  = (const float*)d_in[3];
    const float* a_post = (const float*)d_in[4];
    const float* a_res  = (const float*)d_in[5];
    const float* W      = (const float*)d_in[6];
    const float* Wb     = (const float*)d_in[7];
    float* out = (float*)d_out;

    cudaFuncSetAttribute(k_gemm, cudaFuncAttributeMaxDynamicSharedMemorySize, GEMM_SMEM);
    cudaFuncSetAttribute(k_logits, cudaFuncAttributeMaxDynamicSharedMemorySize, LG_SMEM);

    k_transpose<<<dim3(CN / 32, CN / 32), dim3(32, 8)>>>(W);
    k_phiprep<<<KDIM / 32, dim3(32, 8)>>>(phi);
    k_logits<<<TOK / 32, 256, LG_SMEM>>>(x, b, a_pre, a_post, a_res);
    k_xin<<<TOK * 2, 256>>>(x);
    k_gemm<<<dim3(CN / 128, TOK / 128), 256, GEMM_SMEM>>>(x, Wb, out);
}